// round 2
// baseline (speedup 1.0000x reference)
#include <cuda_runtime.h>
#include <cstdint>
#include <cstddef>

// ---------------- problem constants ----------------
#define BB   1024
#define SS   10
#define NN   36
#define FF   2048
#define DD   2176
#define HH   2176
#define F3   6144
#define MROW (BB*SS)          // 10240
#define PROW (BB*NN)          // 36864

// ---------------- scratch (device globals; no allocation allowed) --------
__device__ float g_pano_ln[(size_t)PROW * DD];
__device__ float g_k      [(size_t)PROW * DD];
__device__ float g_v      [(size_t)PROW * DD];
__device__ float g_s      [(size_t)MROW * DD];
__device__ float g_q      [(size_t)MROW * DD];
__device__ float g_upd    [(size_t)MROW * DD];
__device__ float g_t1     [(size_t)MROW * HH];
__device__ float g_gi     [(size_t)MROW * F3];
__device__ float g_gh     [(size_t)MROW * F3];
__device__ float g_h      [(size_t)MROW * FF];
__device__ float g_hnew   [(size_t)MROW * FF];
__device__ float g_pre    [(size_t)MROW * FF];
__device__ int            g_mask_mode;      // 0=int32, 1=uint8, 2=float32
__device__ unsigned char  g_mask[MROW];

// ---------------- helpers ----------------
__device__ __forceinline__ uint32_t f2tf32(float x) {
    uint32_t r;
    asm("cvt.rna.tf32.f32 %0, %1;" : "=r"(r) : "f"(x));
    return r;
}

// =====================================================================
// Mask dtype detection + normalization.
// The harness widens the bool mask to an unknown dtype. Scan the first
// 10240 bytes (safe for every candidate dtype: uint8=10240B,
// int32/float32=40960B) and classify by byte-position signature:
//   nonzero at pos%4==1           -> uint8 bool (int32/float32 value 1 has 0 there)
//   else nonzero at pos%4 in {2,3} -> float32 (1.0f = 00 00 80 3F)
//   else                           -> int32
// =====================================================================
__global__ void detect_mask(const unsigned char* __restrict__ m)
{
    __shared__ int has1, has23;
    if (threadIdx.x == 0) { has1 = 0; has23 = 0; }
    __syncthreads();
    for (int i = threadIdx.x; i < MROW; i += 256) {
        if (m[i]) {
            const int p = i & 3;
            if (p == 1) atomicOr(&has1, 1);
            if (p >= 2) atomicOr(&has23, 1);
        }
    }
    __syncthreads();
    if (threadIdx.x == 0)
        g_mask_mode = has1 ? 1 : (has23 ? 2 : 0);
}

__global__ void normalize_mask(const void* __restrict__ m)
{
    const int i = blockIdx.x * 256 + threadIdx.x;
    if (i >= MROW) return;
    const int mode = g_mask_mode;
    unsigned char r;
    if (mode == 1)      r = (((const unsigned char*)m)[i] != 0);
    else if (mode == 2) r = (((const float*)m)[i] != 0.0f);
    else                r = (((const int*)m)[i] != 0);
    g_mask[i] = r;
}

// =====================================================================
// Generic TF32 GEMM:  C[M,N] = A[M,K] * W[N,K]^T + bias[N]  (+ epilogue)
// Tiles: 128x128x16, 256 threads (8 warps as 4x2), warp tile 32x64.
// mode 0: +bias ; mode 1: relu(+bias) ; mode 2: +bias + addm[M,N]
// Requires: M%128==0, N%128==0, K%16==0 (true for all shapes here).
// =====================================================================
#define SMS 20   // smem row stride (floats): 16 + 4 pad -> conflict-free frags

__global__ void __launch_bounds__(256, 2)
gemm_tf32(const float* __restrict__ A, const float* __restrict__ W,
          const float* __restrict__ bias, const float* __restrict__ addm,
          float* __restrict__ C, int M, int N, int K, int mode)
{
    __shared__ uint32_t As[2][128 * SMS];
    __shared__ uint32_t Bs[2][128 * SMS];

    const int tid  = threadIdx.x;
    const int lane = tid & 31;
    const int warp = tid >> 5;
    const int gid  = lane >> 2;   // 0..7
    const int tg   = lane & 3;    // 0..3
    const int wm   = warp >> 1;   // 0..3
    const int wn   = warp & 1;    // 0..1

    const int bm0 = blockIdx.y * 128;
    const int bn0 = blockIdx.x * 128;

    const int lr = tid >> 2;         // 0..63
    const int lc = (tid & 3) << 2;   // 0,4,8,12

    const float* Ag = A + (size_t)(bm0 + lr) * K + lc;
    const float* Wg = W + (size_t)(bn0 + lr) * K + lc;
    const size_t rstep = (size_t)64 * K;

    float acc[2][8][4];
#pragma unroll
    for (int i = 0; i < 2; i++)
#pragma unroll
        for (int j = 0; j < 8; j++)
#pragma unroll
            for (int c = 0; c < 4; c++) acc[i][j][c] = 0.f;

    const int ktiles = K >> 4;

    float4 ra0 = *(const float4*)Ag;
    float4 ra1 = *(const float4*)(Ag + rstep);
    float4 rb0 = *(const float4*)Wg;
    float4 rb1 = *(const float4*)(Wg + rstep);
    {
        uint32_t* p;
        p = &As[0][lr * SMS + lc];
        p[0] = f2tf32(ra0.x); p[1] = f2tf32(ra0.y); p[2] = f2tf32(ra0.z); p[3] = f2tf32(ra0.w);
        p = &As[0][(lr + 64) * SMS + lc];
        p[0] = f2tf32(ra1.x); p[1] = f2tf32(ra1.y); p[2] = f2tf32(ra1.z); p[3] = f2tf32(ra1.w);
        p = &Bs[0][lr * SMS + lc];
        p[0] = f2tf32(rb0.x); p[1] = f2tf32(rb0.y); p[2] = f2tf32(rb0.z); p[3] = f2tf32(rb0.w);
        p = &Bs[0][(lr + 64) * SMS + lc];
        p[0] = f2tf32(rb1.x); p[1] = f2tf32(rb1.y); p[2] = f2tf32(rb1.z); p[3] = f2tf32(rb1.w);
    }
    __syncthreads();

    for (int kt = 0; kt < ktiles; kt++) {
        const int cur = kt & 1;
        const bool more = (kt + 1 < ktiles);
        if (more) {
            const float* Ag2 = Ag + (size_t)(kt + 1) * 16;
            const float* Wg2 = Wg + (size_t)(kt + 1) * 16;
            ra0 = *(const float4*)Ag2;
            ra1 = *(const float4*)(Ag2 + rstep);
            rb0 = *(const float4*)Wg2;
            rb1 = *(const float4*)(Wg2 + rstep);
        }

        const uint32_t* Ab = As[cur];
        const uint32_t* Bb = Bs[cur];
#pragma unroll
        for (int ks = 0; ks < 2; ks++) {
            const int k0 = ks * 8;
            uint32_t af[2][4];
#pragma unroll
            for (int mi = 0; mi < 2; mi++) {
                const int r0 = wm * 32 + mi * 16 + gid;
                af[mi][0] = Ab[r0 * SMS + k0 + tg];
                af[mi][1] = Ab[(r0 + 8) * SMS + k0 + tg];
                af[mi][2] = Ab[r0 * SMS + k0 + tg + 4];
                af[mi][3] = Ab[(r0 + 8) * SMS + k0 + tg + 4];
            }
#pragma unroll
            for (int nj = 0; nj < 8; nj++) {
                const int n0 = wn * 64 + nj * 8 + gid;
                const uint32_t bf0 = Bb[n0 * SMS + k0 + tg];
                const uint32_t bf1 = Bb[n0 * SMS + k0 + tg + 4];
#pragma unroll
                for (int mi = 0; mi < 2; mi++) {
                    asm volatile(
                        "mma.sync.aligned.m16n8k8.row.col.f32.tf32.tf32.f32 "
                        "{%0,%1,%2,%3},{%4,%5,%6,%7},{%8,%9},{%0,%1,%2,%3};\n"
                        : "+f"(acc[mi][nj][0]), "+f"(acc[mi][nj][1]),
                          "+f"(acc[mi][nj][2]), "+f"(acc[mi][nj][3])
                        : "r"(af[mi][0]), "r"(af[mi][1]), "r"(af[mi][2]), "r"(af[mi][3]),
                          "r"(bf0), "r"(bf1));
                }
            }
        }

        if (more) {
            const int nxt = cur ^ 1;
            uint32_t* p;
            p = &As[nxt][lr * SMS + lc];
            p[0] = f2tf32(ra0.x); p[1] = f2tf32(ra0.y); p[2] = f2tf32(ra0.z); p[3] = f2tf32(ra0.w);
            p = &As[nxt][(lr + 64) * SMS + lc];
            p[0] = f2tf32(ra1.x); p[1] = f2tf32(ra1.y); p[2] = f2tf32(ra1.z); p[3] = f2tf32(ra1.w);
            p = &Bs[nxt][lr * SMS + lc];
            p[0] = f2tf32(rb0.x); p[1] = f2tf32(rb0.y); p[2] = f2tf32(rb0.z); p[3] = f2tf32(rb0.w);
            p = &Bs[nxt][(lr + 64) * SMS + lc];
            p[0] = f2tf32(rb1.x); p[1] = f2tf32(rb1.y); p[2] = f2tf32(rb1.z); p[3] = f2tf32(rb1.w);
        }
        __syncthreads();
    }

    // epilogue
#pragma unroll
    for (int mi = 0; mi < 2; mi++) {
#pragma unroll
        for (int nj = 0; nj < 8; nj++) {
            const int col = bn0 + wn * 64 + nj * 8 + tg * 2;
            const float2 bv = *(const float2*)&bias[col];
#pragma unroll
            for (int ch = 0; ch < 2; ch++) {
                const int row = bm0 + wm * 32 + mi * 16 + gid + ch * 8;
                float x0 = acc[mi][nj][ch * 2 + 0] + bv.x;
                float x1 = acc[mi][nj][ch * 2 + 1] + bv.y;
                if (mode == 1) {
                    x0 = fmaxf(x0, 0.f);
                    x1 = fmaxf(x1, 0.f);
                } else if (mode == 2) {
                    const float2 av = *(const float2*)&addm[(size_t)row * N + col];
                    x0 += av.x; x1 += av.y;
                }
                float2 o; o.x = x0; o.y = x1;
                *(float2*)&C[(size_t)row * N + col] = o;
            }
        }
    }
}

// =====================================================================
// Row LayerNorm over first 2048 cols + optional tail passthrough.
// One CTA (256 thr) per row. Double accumulators for exactness.
// =====================================================================
__global__ void __launch_bounds__(256)
ln_rows(const float* __restrict__ in, float* __restrict__ out,
        const float* __restrict__ g, const float* __restrict__ b,
        const float* __restrict__ tail_src,
        int in_stride, int out_stride, int tail_stride, int tail_len)
{
    const int row = blockIdx.x;
    const int tid = threadIdx.x;
    const float* x = in + (size_t)row * in_stride;

    const float4 va = *(const float4*)&x[tid * 4];
    const float4 vb = *(const float4*)&x[(tid + 256) * 4];

    double s  = (double)va.x + va.y + va.z + va.w + (double)vb.x + vb.y + vb.z + vb.w;
    double ss = (double)va.x * va.x + (double)va.y * va.y + (double)va.z * va.z + (double)va.w * va.w
              + (double)vb.x * vb.x + (double)vb.y * vb.y + (double)vb.z * vb.z + (double)vb.w * vb.w;

#pragma unroll
    for (int off = 16; off; off >>= 1) {
        s  += __shfl_down_sync(0xffffffffu, s, off);
        ss += __shfl_down_sync(0xffffffffu, ss, off);
    }
    __shared__ double rs[8], rss[8];
    __shared__ float s_mean, s_rstd;
    const int warp = tid >> 5, lane = tid & 31;
    if (lane == 0) { rs[warp] = s; rss[warp] = ss; }
    __syncthreads();
    if (tid == 0) {
        double S = 0.0, SQ = 0.0;
        for (int w = 0; w < 8; w++) { S += rs[w]; SQ += rss[w]; }
        const double mean = S / 2048.0;
        const double var  = SQ / 2048.0 - mean * mean;
        s_mean = (float)mean;
        s_rstd = (float)(1.0 / sqrt(var + 1e-5));
    }
    __syncthreads();
    const float mean = s_mean, rstd = s_rstd;

    float* o = out + (size_t)row * out_stride;
    {
        const int c0 = tid * 4;
        const float4 g4 = *(const float4*)&g[c0];
        const float4 b4 = *(const float4*)&b[c0];
        float4 r;
        r.x = (va.x - mean) * rstd * g4.x + b4.x;
        r.y = (va.y - mean) * rstd * g4.y + b4.y;
        r.z = (va.z - mean) * rstd * g4.z + b4.z;
        r.w = (va.w - mean) * rstd * g4.w + b4.w;
        *(float4*)&o[c0] = r;
    }
    {
        const int c1 = (tid + 256) * 4;
        const float4 g4 = *(const float4*)&g[c1];
        const float4 b4 = *(const float4*)&b[c1];
        float4 r;
        r.x = (vb.x - mean) * rstd * g4.x + b4.x;
        r.y = (vb.y - mean) * rstd * g4.y + b4.y;
        r.z = (vb.z - mean) * rstd * g4.z + b4.z;
        r.w = (vb.w - mean) * rstd * g4.w + b4.w;
        *(float4*)&o[c1] = r;
    }
    if (tail_len) {
        for (int c = tid; c < tail_len; c += 256)
            o[2048 + c] = tail_src[(size_t)row * tail_stride + 2048 + c];
    }
}

// =====================================================================
// Attention: one CTA per batch. dots = q.k^T*scale; softmax over SLOT
// axis (i) per pano column j; updates = attn^T-weighted sum of v.
// attn (last iteration) goes straight to d_out.
// =====================================================================
#define ATT 384
__global__ void __launch_bounds__(ATT)
attn_kernel(const float* __restrict__ q, const float* __restrict__ k,
            const float* __restrict__ v, const unsigned char* __restrict__ mask,
            float* __restrict__ updates, float* __restrict__ attn_out)
{
    const int b = blockIdx.x;
    const int tid = threadIdx.x;

    __shared__ float qs[10][65];
    __shared__ float ks[36][65];
    __shared__ float dots[10][37];
    __shared__ float attns[10][37];

    const int i = tid / 36;
    const int j = tid % 36;
    float acc = 0.f;

    for (int d0 = 0; d0 < DD; d0 += 64) {
        for (int t = tid; t < 640; t += ATT) {
            const int r = t >> 6, c = t & 63;
            qs[r][c] = q[(size_t)(b * 10 + r) * DD + d0 + c];
        }
        for (int t = tid; t < 2304; t += ATT) {
            const int r = t >> 6, c = t & 63;
            ks[r][c] = k[(size_t)(b * 36 + r) * DD + d0 + c];
        }
        __syncthreads();
        if (tid < 360) {
#pragma unroll 16
            for (int dd = 0; dd < 64; dd++)
                acc += qs[i][dd] * ks[j][dd];
        }
        __syncthreads();
    }
    if (tid < 360) dots[i][j] = acc;
    __syncthreads();

    if (tid < 36) {
        const float scale = rsqrtf(2176.0f);
        const int jj = tid;
        bool m[10];
        float dv[10];
        float mx = -3.402823466e38f;
#pragma unroll
        for (int ii = 0; ii < 10; ii++) {
            m[ii] = (mask[b * 10 + ii] != 0);
            dv[ii] = dots[ii][jj] * scale;
            if (!m[ii]) mx = fmaxf(mx, dv[ii]);
        }
        float e[10], sum = 0.f;
#pragma unroll
        for (int ii = 0; ii < 10; ii++) {
            e[ii] = m[ii] ? 0.f : expf(dv[ii] - mx);
            sum += e[ii];
        }
        const float inv = 1.f / sum;
#pragma unroll
        for (int ii = 0; ii < 10; ii++) {
            const float a = e[ii] * inv;
            attns[ii][jj] = a;
            attn_out[(size_t)(b * 10 + ii) * 36 + jj] = a;
        }
    }
    __syncthreads();

    for (int d = tid; d < DD; d += ATT) {
        float u[10];
#pragma unroll
        for (int ii = 0; ii < 10; ii++) u[ii] = 0.f;
        for (int jj = 0; jj < 36; jj++) {
            const float vv = v[(size_t)(b * 36 + jj) * DD + d];
#pragma unroll
            for (int ii = 0; ii < 10; ii++) u[ii] += attns[ii][jj] * vv;
        }
#pragma unroll
        for (int ii = 0; ii < 10; ii++)
            updates[(size_t)(b * 10 + ii) * DD + d] = u[ii];
    }
}

// ---------------- GRU elementwise ----------------
__global__ void __launch_bounds__(256)
gru_kernel(const float* __restrict__ gi, const float* __restrict__ gh,
           const float* __restrict__ h, float* __restrict__ hnew)
{
    const size_t idx = (size_t)blockIdx.x * 256 + threadIdx.x;
    const size_t row = idx >> 11;
    const size_t f   = idx & 2047;
    const size_t gb  = row * (size_t)F3 + f;
    const float ir = gi[gb], iz = gi[gb + 2048], in_ = gi[gb + 4096];
    const float hr = gh[gb], hz = gh[gb + 2048], hn  = gh[gb + 4096];
    const float r = 1.f / (1.f + expf(-(ir + hr)));
    const float z = 1.f / (1.f + expf(-(iz + hz)));
    const float n = tanhf(in_ + r * hn);
    hnew[idx] = (1.f - z) * n + z * h[idx];
}

// ---------------- misc copies ----------------
__global__ void __launch_bounds__(256)
init_h(const float* __restrict__ cand, float* __restrict__ h)
{
    const size_t idx = (size_t)blockIdx.x * 256 + threadIdx.x;
    const size_t row = idx >> 11;
    const size_t f   = idx & 2047;
    h[idx] = cand[row * (size_t)DD + f];
}

__global__ void __launch_bounds__(256)
write_slots(const float* __restrict__ h, const float* __restrict__ cand,
            float* __restrict__ out)
{
    const size_t idx = (size_t)blockIdx.x * 256 + threadIdx.x;
    const size_t row = idx / DD;
    const size_t c   = idx % DD;
    out[idx] = (c < 2048) ? h[row * (size_t)FF + c] : cand[idx];
}

// =====================================================================
// launch
// =====================================================================
extern "C" void kernel_launch(void* const* d_in, const int* in_sizes, int n_in,
                              void* d_out, int out_size)
{
    const float* cand  = (const float*)d_in[0];
    const float* pano  = (const float*)d_in[1];
    const void*  maskp = d_in[2];
    const float* Wq = (const float*)d_in[3];  const float* bq = (const float*)d_in[4];
    const float* Wk = (const float*)d_in[5];  const float* bk = (const float*)d_in[6];
    const float* Wv = (const float*)d_in[7];  const float* bv = (const float*)d_in[8];
    const float* W_ih = (const float*)d_in[9];  const float* b_ih = (const float*)d_in[10];
    const float* W_hh = (const float*)d_in[11]; const float* b_hh = (const float*)d_in[12];
    const float* W1 = (const float*)d_in[13]; const float* b1 = (const float*)d_in[14];
    const float* W2 = (const float*)d_in[15]; const float* b2 = (const float*)d_in[16];
    const float* ln_in_g = (const float*)d_in[17]; const float* ln_in_b = (const float*)d_in[18];
    const float* ln_sl_g = (const float*)d_in[19]; const float* ln_sl_b = (const float*)d_in[20];
    const float* ln_pr_g = (const float*)d_in[21]; const float* ln_pr_b = (const float*)d_in[22];

    float* out      = (float*)d_out;
    float* out_attn = out + (size_t)MROW * DD;

    float *p_pano, *p_k, *p_v, *p_s, *p_q, *p_upd, *p_t1, *p_gi, *p_gh, *p_h, *p_hnew, *p_pre;
    unsigned char* p_mask;
    cudaGetSymbolAddress((void**)&p_pano, g_pano_ln);
    cudaGetSymbolAddress((void**)&p_k,    g_k);
    cudaGetSymbolAddress((void**)&p_v,    g_v);
    cudaGetSymbolAddress((void**)&p_s,    g_s);
    cudaGetSymbolAddress((void**)&p_q,    g_q);
    cudaGetSymbolAddress((void**)&p_upd,  g_upd);
    cudaGetSymbolAddress((void**)&p_t1,   g_t1);
    cudaGetSymbolAddress((void**)&p_gi,   g_gi);
    cudaGetSymbolAddress((void**)&p_gh,   g_gh);
    cudaGetSymbolAddress((void**)&p_h,    g_h);
    cudaGetSymbolAddress((void**)&p_hnew, g_hnew);
    cudaGetSymbolAddress((void**)&p_pre,  g_pre);
    cudaGetSymbolAddress((void**)&p_mask, g_mask);

    // mask dtype detection + canonicalization
    detect_mask<<<1, 256>>>((const unsigned char*)maskp);
    normalize_mask<<<(MROW + 255) / 256, 256>>>(maskp);

    // pano LN (first F cols, tail passthrough)
    ln_rows<<<PROW, 256>>>(pano, p_pano, ln_in_g, ln_in_b, pano, DD, DD, DD, DD - FF);

    // k, v projections
    {
        dim3 grd(DD / 128, PROW / 128);
        gemm_tf32<<<grd, 256>>>(p_pano, Wk, bk, nullptr, p_k, PROW, DD, DD, 0);
        gemm_tf32<<<grd, 256>>>(p_pano, Wv, bv, nullptr, p_v, PROW, DD, DD, 0);
    }

    // h0 = cand[..., :F]
    init_h<<<(MROW * FF) / 256, 256>>>(cand, p_h);

    for (int it = 0; it < 3; it++) {
        // s = concat(LN(h), angle)
        ln_rows<<<MROW, 256>>>(p_h, p_s, ln_sl_g, ln_sl_b, cand, FF, DD, DD, DD - FF);
        // q = s Wq^T + bq
        {
            dim3 grd(DD / 128, MROW / 128);
            gemm_tf32<<<grd, 256>>>(p_s, Wq, bq, nullptr, p_q, MROW, DD, DD, 0);
        }
        // attention (writes attn to d_out, updates to scratch)
        attn_kernel<<<BB, ATT>>>(p_q, p_k, p_v, p_mask, p_upd, out_attn);
        // gi = upd W_ih^T + b_ih ; gh = h W_hh^T + b_hh
        {
            dim3 grd(F3 / 128, MROW / 128);
            gemm_tf32<<<grd, 256>>>(p_upd, W_ih, b_ih, nullptr, p_gi, MROW, F3, DD, 0);
            gemm_tf32<<<grd, 256>>>(p_h,   W_hh, b_hh, nullptr, p_gh, MROW, F3, FF, 0);
        }
        // GRU
        gru_kernel<<<(MROW * FF) / 256, 256>>>(p_gi, p_gh, p_h, p_hnew);
        // pre = LN(h_new)
        ln_rows<<<MROW, 256>>>(p_hnew, p_pre, ln_pr_g, ln_pr_b, nullptr, FF, FF, 0, 0);
        // t1 = relu(pre W1^T + b1)
        {
            dim3 grd(HH / 128, MROW / 128);
            gemm_tf32<<<grd, 256>>>(p_pre, W1, b1, nullptr, p_t1, MROW, HH, FF, 1);
        }
        // h = h_new + (t1 W2^T + b2)
        {
            dim3 grd(FF / 128, MROW / 128);
            gemm_tf32<<<grd, 256>>>(p_t1, W2, b2, p_hnew, p_h, MROW, FF, HH, 2);
        }
    }

    // slots output = concat(h, angle)
    write_slots<<<(MROW * DD) / 256, 256>>>(p_h, cand, out);
}

// round 3
// speedup vs baseline: 1.1080x; 1.1080x over previous
#include <cuda_runtime.h>
#include <cstdint>
#include <cstddef>

// ---------------- problem constants ----------------
#define BB   1024
#define SS   10
#define NN   36
#define FF   2048
#define DD   2176
#define HH   2176
#define F3   6144
#define MROW (BB*SS)          // 10240
#define PROW (BB*NN)          // 36864

#define SZ_QKV (2176*2176)
#define SZ_IH  (6144*2176)
#define SZ_HH  (6144*2048)
#define SZ_W1  (2176*2048)
#define SZ_W2  (2048*2176)

// ---------------- scratch (device globals; no allocation allowed) --------
__device__ float g_pano_ln[(size_t)PROW * DD];
__device__ float g_k      [(size_t)PROW * DD];
__device__ float g_v      [(size_t)PROW * DD];
__device__ float g_s      [(size_t)MROW * DD];
__device__ float g_q      [(size_t)MROW * DD];
__device__ float g_upd    [(size_t)MROW * DD];
__device__ float g_t1     [(size_t)MROW * HH];
__device__ float g_gi     [(size_t)MROW * F3];
__device__ float g_gh     [(size_t)MROW * F3];
__device__ float g_h      [(size_t)MROW * FF];
__device__ float g_hr     [(size_t)MROW * FF];   // tf32-rounded copy of h
__device__ float g_hnew   [(size_t)MROW * FF];
__device__ float g_pre    [(size_t)MROW * FF];
__device__ float g_wtf    [(size_t)3*SZ_QKV + SZ_IH + SZ_HH + SZ_W1 + SZ_W2];
__device__ int            g_mask_mode;
__device__ unsigned char  g_mask[MROW];

// ---------------- helpers ----------------
__device__ __forceinline__ float roundtf(float x) {
    uint32_t r;
    asm("cvt.rna.tf32.f32 %0, %1;" : "=r"(r) : "f"(x));
    return __uint_as_float(r);
}

__device__ __forceinline__ void cp16(float* dst, const float* src) {
    uint32_t d = (uint32_t)__cvta_generic_to_shared(dst);
    asm volatile("cp.async.cg.shared.global [%0], [%1], 16;" :: "r"(d), "l"(src));
}
__device__ __forceinline__ void cp_commit() {
    asm volatile("cp.async.commit_group;");
}
__device__ __forceinline__ void cp_wait2() {
    asm volatile("cp.async.wait_group 2;");
}

// =====================================================================
// Mask dtype detection + normalization (bool widened to unknown dtype).
// =====================================================================
__global__ void detect_mask(const unsigned char* __restrict__ m)
{
    __shared__ int has1, has23;
    if (threadIdx.x == 0) { has1 = 0; has23 = 0; }
    __syncthreads();
    for (int i = threadIdx.x; i < MROW; i += 256) {
        if (m[i]) {
            const int p = i & 3;
            if (p == 1) atomicOr(&has1, 1);
            if (p >= 2) atomicOr(&has23, 1);
        }
    }
    __syncthreads();
    if (threadIdx.x == 0)
        g_mask_mode = has1 ? 1 : (has23 ? 2 : 0);
}

__global__ void normalize_mask(const void* __restrict__ m)
{
    const int i = blockIdx.x * 256 + threadIdx.x;
    if (i >= MROW) return;
    const int mode = g_mask_mode;
    unsigned char r;
    if (mode == 1)      r = (((const unsigned char*)m)[i] != 0);
    else if (mode == 2) r = (((const float*)m)[i] != 0.0f);
    else                r = (((const int*)m)[i] != 0);
    g_mask[i] = r;
}

// ---------------- tf32-round copy (weights) ----------------
__global__ void __launch_bounds__(256)
round_copy(const float* __restrict__ s, float* __restrict__ d, int n4)
{
    const int i = blockIdx.x * 256 + threadIdx.x;
    if (i >= n4) return;
    float4 v = ((const float4*)s)[i];
    v.x = roundtf(v.x); v.y = roundtf(v.y); v.z = roundtf(v.z); v.w = roundtf(v.w);
    ((float4*)d)[i] = v;
}

// =====================================================================
// TF32 GEMM:  C[M,N] = A[M,K] * W[N,K]^T + bias[N]
// A and W MUST be pre-rounded to tf32-representable floats.
// 128x128 tile, 256 thr (8 warps 4x2, warp 32x64), 4-stage cp.async.
// mode 0: C=acc+bias
// mode 1: C=roundtf(relu(acc+bias))
// mode 2: C=acc+bias+addm ; Cr=roundtf(C)
// =====================================================================
#define SMS 20
#define STAGES 4
#define STAGE_F (128*SMS)
#define GEMM_SMEM (STAGES*STAGE_F*2*4)

__global__ void __launch_bounds__(256)
gemm_tf32(const float* __restrict__ A, const float* __restrict__ W,
          const float* __restrict__ bias, const float* __restrict__ addm,
          float* __restrict__ C, float* __restrict__ Cr,
          int M, int N, int K, int mode)
{
    extern __shared__ float sm[];
    float* As = sm;
    float* Bs = sm + STAGES * STAGE_F;

    const int tid  = threadIdx.x;
    const int lane = tid & 31;
    const int warp = tid >> 5;
    const int gid  = lane >> 2;
    const int tg   = lane & 3;
    const int wm   = warp >> 1;
    const int wn   = warp & 1;

    const int bm0 = blockIdx.y * 128;
    const int bn0 = blockIdx.x * 128;

    const int lr = tid >> 2;
    const int lc = (tid & 3) << 2;

    const float* Ag = A + (size_t)(bm0 + lr) * K + lc;
    const float* Wg = W + (size_t)(bn0 + lr) * K + lc;
    const size_t rstep = (size_t)64 * K;

    const int ktiles = K >> 4;

    // prologue: prefetch 3 stages
#pragma unroll
    for (int s = 0; s < 3; s++) {
        if (s < ktiles) {
            const float* a0 = Ag + s * 16;
            const float* w0 = Wg + s * 16;
            float* as = As + s * STAGE_F;
            float* bs = Bs + s * STAGE_F;
            cp16(as + lr * SMS + lc, a0);
            cp16(as + (lr + 64) * SMS + lc, a0 + rstep);
            cp16(bs + lr * SMS + lc, w0);
            cp16(bs + (lr + 64) * SMS + lc, w0 + rstep);
        }
        cp_commit();
    }
    cp_wait2();
    __syncthreads();

    float acc[2][8][4];
#pragma unroll
    for (int i = 0; i < 2; i++)
#pragma unroll
        for (int j = 0; j < 8; j++)
#pragma unroll
            for (int c = 0; c < 4; c++) acc[i][j][c] = 0.f;

    for (int kt = 0; kt < ktiles; kt++) {
        const int s = kt & (STAGES - 1);

        // issue stage kt+3 (overwrites buffer consumed at kt-1; safe: all
        // threads passed the sync at end of iteration kt-1 after reading it)
        const int kn = kt + 3;
        if (kn < ktiles) {
            const int sn = kn & (STAGES - 1);
            const float* a0 = Ag + (size_t)kn * 16;
            const float* w0 = Wg + (size_t)kn * 16;
            float* as = As + sn * STAGE_F;
            float* bs = Bs + sn * STAGE_F;
            cp16(as + lr * SMS + lc, a0);
            cp16(as + (lr + 64) * SMS + lc, a0 + rstep);
            cp16(bs + lr * SMS + lc, w0);
            cp16(bs + (lr + 64) * SMS + lc, w0 + rstep);
        }
        cp_commit();

        const uint32_t* Ab = (const uint32_t*)(As + s * STAGE_F);
        const uint32_t* Bb = (const uint32_t*)(Bs + s * STAGE_F);
#pragma unroll
        for (int ks = 0; ks < 2; ks++) {
            const int k0 = ks * 8;
            uint32_t af[2][4];
#pragma unroll
            for (int mi = 0; mi < 2; mi++) {
                const int r0 = wm * 32 + mi * 16 + gid;
                af[mi][0] = Ab[r0 * SMS + k0 + tg];
                af[mi][1] = Ab[(r0 + 8) * SMS + k0 + tg];
                af[mi][2] = Ab[r0 * SMS + k0 + tg + 4];
                af[mi][3] = Ab[(r0 + 8) * SMS + k0 + tg + 4];
            }
#pragma unroll
            for (int nj = 0; nj < 8; nj++) {
                const int n0 = wn * 64 + nj * 8 + gid;
                const uint32_t bf0 = Bb[n0 * SMS + k0 + tg];
                const uint32_t bf1 = Bb[n0 * SMS + k0 + tg + 4];
#pragma unroll
                for (int mi = 0; mi < 2; mi++) {
                    asm volatile(
                        "mma.sync.aligned.m16n8k8.row.col.f32.tf32.tf32.f32 "
                        "{%0,%1,%2,%3},{%4,%5,%6,%7},{%8,%9},{%0,%1,%2,%3};\n"
                        : "+f"(acc[mi][nj][0]), "+f"(acc[mi][nj][1]),
                          "+f"(acc[mi][nj][2]), "+f"(acc[mi][nj][3])
                        : "r"(af[mi][0]), "r"(af[mi][1]), "r"(af[mi][2]), "r"(af[mi][3]),
                          "r"(bf0), "r"(bf1));
                }
            }
        }

        cp_wait2();
        __syncthreads();
    }

    // epilogue
#pragma unroll
    for (int mi = 0; mi < 2; mi++) {
#pragma unroll
        for (int nj = 0; nj < 8; nj++) {
            const int col = bn0 + wn * 64 + nj * 8 + tg * 2;
            const float2 bv = *(const float2*)&bias[col];
#pragma unroll
            for (int ch = 0; ch < 2; ch++) {
                const int row = bm0 + wm * 32 + mi * 16 + gid + ch * 8;
                float x0 = acc[mi][nj][ch * 2 + 0] + bv.x;
                float x1 = acc[mi][nj][ch * 2 + 1] + bv.y;
                if (mode == 1) {
                    x0 = roundtf(fmaxf(x0, 0.f));
                    x1 = roundtf(fmaxf(x1, 0.f));
                } else if (mode == 2) {
                    const float2 av = *(const float2*)&addm[(size_t)row * N + col];
                    x0 += av.x; x1 += av.y;
                    float2 r; r.x = roundtf(x0); r.y = roundtf(x1);
                    *(float2*)&Cr[(size_t)row * N + col] = r;
                }
                float2 o; o.x = x0; o.y = x1;
                *(float2*)&C[(size_t)row * N + col] = o;
            }
        }
    }
}

// =====================================================================
// Row LayerNorm over first 2048 cols + optional tail passthrough.
// round_out: outputs (incl. tail) rounded to tf32 grid (consumed as GEMM A).
// =====================================================================
__global__ void __launch_bounds__(256)
ln_rows(const float* __restrict__ in, float* __restrict__ out,
        const float* __restrict__ g, const float* __restrict__ b,
        const float* __restrict__ tail_src,
        int in_stride, int out_stride, int tail_stride, int tail_len,
        int round_out)
{
    const int row = blockIdx.x;
    const int tid = threadIdx.x;
    const float* x = in + (size_t)row * in_stride;

    const float4 va = *(const float4*)&x[tid * 4];
    const float4 vb = *(const float4*)&x[(tid + 256) * 4];

    double s  = (double)va.x + va.y + va.z + va.w + (double)vb.x + vb.y + vb.z + vb.w;
    double ss = (double)va.x * va.x + (double)va.y * va.y + (double)va.z * va.z + (double)va.w * va.w
              + (double)vb.x * vb.x + (double)vb.y * vb.y + (double)vb.z * vb.z + (double)vb.w * vb.w;

#pragma unroll
    for (int off = 16; off; off >>= 1) {
        s  += __shfl_down_sync(0xffffffffu, s, off);
        ss += __shfl_down_sync(0xffffffffu, ss, off);
    }
    __shared__ double rs[8], rss[8];
    __shared__ float s_mean, s_rstd;
    const int warp = tid >> 5, lane = tid & 31;
    if (lane == 0) { rs[warp] = s; rss[warp] = ss; }
    __syncthreads();
    if (tid == 0) {
        double S = 0.0, SQ = 0.0;
        for (int w = 0; w < 8; w++) { S += rs[w]; SQ += rss[w]; }
        const double mean = S / 2048.0;
        const double var  = SQ / 2048.0 - mean * mean;
        s_mean = (float)mean;
        s_rstd = (float)(1.0 / sqrt(var + 1e-5));
    }
    __syncthreads();
    const float mean = s_mean, rstd = s_rstd;

    float* o = out + (size_t)row * out_stride;
    {
        const int c0 = tid * 4;
        const float4 g4 = *(const float4*)&g[c0];
        const float4 b4 = *(const float4*)&b[c0];
        float4 r;
        r.x = (va.x - mean) * rstd * g4.x + b4.x;
        r.y = (va.y - mean) * rstd * g4.y + b4.y;
        r.z = (va.z - mean) * rstd * g4.z + b4.z;
        r.w = (va.w - mean) * rstd * g4.w + b4.w;
        if (round_out) { r.x = roundtf(r.x); r.y = roundtf(r.y); r.z = roundtf(r.z); r.w = roundtf(r.w); }
        *(float4*)&o[c0] = r;
    }
    {
        const int c1 = (tid + 256) * 4;
        const float4 g4 = *(const float4*)&g[c1];
        const float4 b4 = *(const float4*)&b[c1];
        float4 r;
        r.x = (vb.x - mean) * rstd * g4.x + b4.x;
        r.y = (vb.y - mean) * rstd * g4.y + b4.y;
        r.z = (vb.z - mean) * rstd * g4.z + b4.z;
        r.w = (vb.w - mean) * rstd * g4.w + b4.w;
        if (round_out) { r.x = roundtf(r.x); r.y = roundtf(r.y); r.z = roundtf(r.z); r.w = roundtf(r.w); }
        *(float4*)&o[c1] = r;
    }
    if (tail_len) {
        for (int c = tid; c < tail_len; c += 256) {
            float t = tail_src[(size_t)row * tail_stride + 2048 + c];
            o[2048 + c] = round_out ? roundtf(t) : t;
        }
    }
}

// =====================================================================
// Attention: one CTA per batch. softmax over SLOT axis per pano column.
// updates written tf32-rounded (consumed only as GEMM A by W_ih).
// =====================================================================
#define ATT 384
__global__ void __launch_bounds__(ATT)
attn_kernel(const float* __restrict__ q, const float* __restrict__ k,
            const float* __restrict__ v, const unsigned char* __restrict__ mask,
            float* __restrict__ updates, float* __restrict__ attn_out)
{
    const int b = blockIdx.x;
    const int tid = threadIdx.x;

    __shared__ float qs[10][65];
    __shared__ float ks[36][65];
    __shared__ float dots[10][37];
    __shared__ float attns[10][37];

    const int i = tid / 36;
    const int j = tid % 36;
    float acc = 0.f;

    for (int d0 = 0; d0 < DD; d0 += 64) {
        for (int t = tid; t < 640; t += ATT) {
            const int r = t >> 6, c = t & 63;
            qs[r][c] = q[(size_t)(b * 10 + r) * DD + d0 + c];
        }
        for (int t = tid; t < 2304; t += ATT) {
            const int r = t >> 6, c = t & 63;
            ks[r][c] = k[(size_t)(b * 36 + r) * DD + d0 + c];
        }
        __syncthreads();
        if (tid < 360) {
#pragma unroll 16
            for (int dd = 0; dd < 64; dd++)
                acc += qs[i][dd] * ks[j][dd];
        }
        __syncthreads();
    }
    if (tid < 360) dots[i][j] = acc;
    __syncthreads();

    if (tid < 36) {
        const float scale = rsqrtf(2176.0f);
        const int jj = tid;
        bool m[10];
        float dv[10];
        float mx = -3.402823466e38f;
#pragma unroll
        for (int ii = 0; ii < 10; ii++) {
            m[ii] = (mask[b * 10 + ii] != 0);
            dv[ii] = dots[ii][jj] * scale;
            if (!m[ii]) mx = fmaxf(mx, dv[ii]);
        }
        float e[10], sum = 0.f;
#pragma unroll
        for (int ii = 0; ii < 10; ii++) {
            e[ii] = m[ii] ? 0.f : expf(dv[ii] - mx);
            sum += e[ii];
        }
        const float inv = 1.f / sum;
#pragma unroll
        for (int ii = 0; ii < 10; ii++) {
            const float a = e[ii] * inv;
            attns[ii][jj] = a;
            attn_out[(size_t)(b * 10 + ii) * 36 + jj] = a;
        }
    }
    __syncthreads();

    for (int d = tid; d < DD; d += ATT) {
        float u[10];
#pragma unroll
        for (int ii = 0; ii < 10; ii++) u[ii] = 0.f;
        for (int jj = 0; jj < 36; jj++) {
            const float vv = v[(size_t)(b * 36 + jj) * DD + d];
#pragma unroll
            for (int ii = 0; ii < 10; ii++) u[ii] += attns[ii][jj] * vv;
        }
#pragma unroll
        for (int ii = 0; ii < 10; ii++)
            updates[(size_t)(b * 10 + ii) * DD + d] = roundtf(u[ii]);
    }
}

// ---------------- GRU elementwise ----------------
__global__ void __launch_bounds__(256)
gru_kernel(const float* __restrict__ gi, const float* __restrict__ gh,
           const float* __restrict__ h, float* __restrict__ hnew)
{
    const size_t idx = (size_t)blockIdx.x * 256 + threadIdx.x;
    const size_t row = idx >> 11;
    const size_t f   = idx & 2047;
    const size_t gb  = row * (size_t)F3 + f;
    const float ir = gi[gb], iz = gi[gb + 2048], in_ = gi[gb + 4096];
    const float hr = gh[gb], hz = gh[gb + 2048], hn  = gh[gb + 4096];
    const float r = 1.f / (1.f + expf(-(ir + hr)));
    const float z = 1.f / (1.f + expf(-(iz + hz)));
    const float n = tanhf(in_ + r * hn);
    hnew[idx] = (1.f - z) * n + z * h[idx];
}

// ---------------- misc copies ----------------
__global__ void __launch_bounds__(256)
init_h(const float* __restrict__ cand, float* __restrict__ h, float* __restrict__ hr)
{
    const size_t idx = (size_t)blockIdx.x * 256 + threadIdx.x;
    const size_t row = idx >> 11;
    const size_t f   = idx & 2047;
    const float x = cand[row * (size_t)DD + f];
    h[idx]  = x;
    hr[idx] = roundtf(x);
}

__global__ void __launch_bounds__(256)
write_slots(const float* __restrict__ h, const float* __restrict__ cand,
            float* __restrict__ out)
{
    const size_t idx = (size_t)blockIdx.x * 256 + threadIdx.x;
    const size_t row = idx / DD;
    const size_t c   = idx % DD;
    out[idx] = (c < 2048) ? h[row * (size_t)FF + c] : cand[idx];
}

// =====================================================================
// launch
// =====================================================================
extern "C" void kernel_launch(void* const* d_in, const int* in_sizes, int n_in,
                              void* d_out, int out_size)
{
    const float* cand  = (const float*)d_in[0];
    const float* pano  = (const float*)d_in[1];
    const void*  maskp = d_in[2];
    const float* Wq = (const float*)d_in[3];  const float* bq = (const float*)d_in[4];
    const float* Wk = (const float*)d_in[5];  const float* bk = (const float*)d_in[6];
    const float* Wv = (const float*)d_in[7];  const float* bv = (const float*)d_in[8];
    const float* W_ih = (const float*)d_in[9];  const float* b_ih = (const float*)d_in[10];
    const float* W_hh = (const float*)d_in[11]; const float* b_hh = (const float*)d_in[12];
    const float* W1 = (const float*)d_in[13]; const float* b1 = (const float*)d_in[14];
    const float* W2 = (const float*)d_in[15]; const float* b2 = (const float*)d_in[16];
    const float* ln_in_g = (const float*)d_in[17]; const float* ln_in_b = (const float*)d_in[18];
    const float* ln_sl_g = (const float*)d_in[19]; const float* ln_sl_b = (const float*)d_in[20];
    const float* ln_pr_g = (const float*)d_in[21]; const float* ln_pr_b = (const float*)d_in[22];

    float* out      = (float*)d_out;
    float* out_attn = out + (size_t)MROW * DD;

    float *p_pano, *p_k, *p_v, *p_s, *p_q, *p_upd, *p_t1, *p_gi, *p_gh;
    float *p_h, *p_hr, *p_hnew, *p_pre, *p_w;
    unsigned char* p_mask;
    cudaGetSymbolAddress((void**)&p_pano, g_pano_ln);
    cudaGetSymbolAddress((void**)&p_k,    g_k);
    cudaGetSymbolAddress((void**)&p_v,    g_v);
    cudaGetSymbolAddress((void**)&p_s,    g_s);
    cudaGetSymbolAddress((void**)&p_q,    g_q);
    cudaGetSymbolAddress((void**)&p_upd,  g_upd);
    cudaGetSymbolAddress((void**)&p_t1,   g_t1);
    cudaGetSymbolAddress((void**)&p_gi,   g_gi);
    cudaGetSymbolAddress((void**)&p_gh,   g_gh);
    cudaGetSymbolAddress((void**)&p_h,    g_h);
    cudaGetSymbolAddress((void**)&p_hr,   g_hr);
    cudaGetSymbolAddress((void**)&p_hnew, g_hnew);
    cudaGetSymbolAddress((void**)&p_pre,  g_pre);
    cudaGetSymbolAddress((void**)&p_w,    g_wtf);
    cudaGetSymbolAddress((void**)&p_mask, g_mask);

    cudaFuncSetAttribute(gemm_tf32, cudaFuncAttributeMaxDynamicSharedMemorySize, GEMM_SMEM);

    // rounded weight copies (one-time per replay)
    float* rWq = p_w;
    float* rWk = rWq + SZ_QKV;
    float* rWv = rWk + SZ_QKV;
    float* rWih = rWv + SZ_QKV;
    float* rWhh = rWih + SZ_IH;
    float* rW1  = rWhh + SZ_HH;
    float* rW2  = rW1 + SZ_W1;
    round_copy<<<(SZ_QKV/4 + 255)/256, 256>>>(Wq, rWq, SZ_QKV/4);
    round_copy<<<(SZ_QKV/4 + 255)/256, 256>>>(Wk, rWk, SZ_QKV/4);
    round_copy<<<(SZ_QKV/4 + 255)/256, 256>>>(Wv, rWv, SZ_QKV/4);
    round_copy<<<(SZ_IH /4 + 255)/256, 256>>>(W_ih, rWih, SZ_IH/4);
    round_copy<<<(SZ_HH /4 + 255)/256, 256>>>(W_hh, rWhh, SZ_HH/4);
    round_copy<<<(SZ_W1 /4 + 255)/256, 256>>>(W1, rW1, SZ_W1/4);
    round_copy<<<(SZ_W2 /4 + 255)/256, 256>>>(W2, rW2, SZ_W2/4);

    // mask dtype detection + canonicalization
    detect_mask<<<1, 256>>>((const unsigned char*)maskp);
    normalize_mask<<<(MROW + 255) / 256, 256>>>(maskp);

    // pano LN (rounded: consumed only as GEMM A for k/v)
    ln_rows<<<PROW, 256>>>(pano, p_pano, ln_in_g, ln_in_b, pano, DD, DD, DD, DD - FF, 1);

    // k, v projections
    {
        dim3 grd(DD / 128, PROW / 128);
        gemm_tf32<<<grd, 256, GEMM_SMEM>>>(p_pano, rWk, bk, nullptr, p_k, nullptr, PROW, DD, DD, 0);
        gemm_tf32<<<grd, 256, GEMM_SMEM>>>(p_pano, rWv, bv, nullptr, p_v, nullptr, PROW, DD, DD, 0);
    }

    // h0 = cand[..., :F] (exact + rounded shadow)
    init_h<<<(MROW * FF) / 256, 256>>>(cand, p_h, p_hr);

    for (int it = 0; it < 3; it++) {
        // s = concat(LN(h), angle), rounded (consumed only by q GEMM)
        ln_rows<<<MROW, 256>>>(p_h, p_s, ln_sl_g, ln_sl_b, cand, FF, DD, DD, DD - FF, 1);
        {
            dim3 grd(DD / 128, MROW / 128);
            gemm_tf32<<<grd, 256, GEMM_SMEM>>>(p_s, rWq, bq, nullptr, p_q, nullptr, MROW, DD, DD, 0);
        }
        attn_kernel<<<BB, ATT>>>(p_q, p_k, p_v, p_mask, p_upd, out_attn);
        {
            dim3 grd(F3 / 128, MROW / 128);
            gemm_tf32<<<grd, 256, GEMM_SMEM>>>(p_upd, rWih, b_ih, nullptr, p_gi, nullptr, MROW, F3, DD, 0);
            gemm_tf32<<<grd, 256, GEMM_SMEM>>>(p_hr,  rWhh, b_hh, nullptr, p_gh, nullptr, MROW, F3, FF, 0);
        }
        gru_kernel<<<(MROW * FF) / 256, 256>>>(p_gi, p_gh, p_h, p_hnew);
        // pre = LN(h_new), rounded (consumed only by W1 GEMM)
        ln_rows<<<MROW, 256>>>(p_hnew, p_pre, ln_pr_g, ln_pr_b, nullptr, FF, FF, 0, 0, 1);
        {
            dim3 grd(HH / 128, MROW / 128);
            gemm_tf32<<<grd, 256, GEMM_SMEM>>>(p_pre, rW1, b1, nullptr, p_t1, nullptr, MROW, HH, FF, 1);
        }
        {
            dim3 grd(FF / 128, MROW / 128);
            gemm_tf32<<<grd, 256, GEMM_SMEM>>>(p_t1, rW2, b2, p_hnew, p_h, p_hr, MROW, FF, HH, 2);
        }
    }

    // slots output = concat(h, angle)
    write_slots<<<(MROW * DD) / 256, 256>>>(p_h, cand, out);
}

// round 5
// speedup vs baseline: 1.2961x; 1.1698x over previous
#include <cuda_runtime.h>
#include <cstdint>
#include <cstddef>

// ---------------- problem constants ----------------
#define BB   1024
#define SS   10
#define NN   36
#define FF   2048
#define DD   2176
#define HH   2176
#define F3   6144
#define MROW (BB*SS)          // 10240
#define PROW (BB*NN)          // 36864

#define SZ_QKV (2176*2176)
#define SZ_IH  (6144*2176)
#define SZ_HH  (6144*2048)
#define SZ_W1  (2176*2048)
#define SZ_W2  (2048*2176)

// ---------------- scratch (device globals; no allocation allowed) --------
__device__ float g_pano_ln[(size_t)PROW * DD];
__device__ float g_k      [(size_t)PROW * DD];
__device__ float g_v      [(size_t)PROW * DD];
__device__ float g_s      [(size_t)MROW * DD];
__device__ float g_q      [(size_t)MROW * DD];
__device__ float g_upd    [(size_t)MROW * DD];
__device__ float g_t1     [(size_t)MROW * HH];
__device__ float g_gi     [(size_t)MROW * F3];
__device__ float g_gh     [(size_t)MROW * F3];
__device__ float g_h      [(size_t)MROW * FF];
__device__ float g_hr     [(size_t)MROW * FF];   // tf32-rounded copy of h
__device__ float g_hnew   [(size_t)MROW * FF];
__device__ float g_pre    [(size_t)MROW * FF];
__device__ float g_wtf    [(size_t)3*SZ_QKV + SZ_IH + SZ_HH + SZ_W1 + SZ_W2];
__device__ int            g_mask_mode;
__device__ unsigned char  g_mask[MROW];

// ---------------- helpers ----------------
__device__ __forceinline__ float roundtf(float x) {
    uint32_t r;
    asm("cvt.rna.tf32.f32 %0, %1;" : "=r"(r) : "f"(x));
    return __uint_as_float(r);
}

__device__ __forceinline__ void cp16(void* dst, const float* src) {
    uint32_t d = (uint32_t)__cvta_generic_to_shared(dst);
    asm volatile("cp.async.cg.shared.global [%0], [%1], 16;" :: "r"(d), "l"(src));
}

__device__ __forceinline__ uint32_t smem_u32(const void* p) {
    uint32_t a;
    asm("{ .reg .u64 t; cvta.to.shared.u64 t, %1; cvt.u32.u64 %0, t; }" : "=r"(a) : "l"(p));
    return a;
}

__device__ __forceinline__ void ldsm4(uint32_t& d0, uint32_t& d1, uint32_t& d2,
                                      uint32_t& d3, uint32_t addr) {
    asm volatile("ldmatrix.sync.aligned.m8n8.x4.shared.b16 {%0,%1,%2,%3}, [%4];"
                 : "=r"(d0), "=r"(d1), "=r"(d2), "=r"(d3) : "r"(addr));
}

// =====================================================================
// Mask dtype detection + normalization (bool widened to unknown dtype).
// =====================================================================
__global__ void detect_mask(const unsigned char* __restrict__ m)
{
    __shared__ int has1, has23;
    if (threadIdx.x == 0) { has1 = 0; has23 = 0; }
    __syncthreads();
    for (int i = threadIdx.x; i < MROW; i += 256) {
        if (m[i]) {
            const int p = i & 3;
            if (p == 1) atomicOr(&has1, 1);
            if (p >= 2) atomicOr(&has23, 1);
        }
    }
    __syncthreads();
    if (threadIdx.x == 0)
        g_mask_mode = has1 ? 1 : (has23 ? 2 : 0);
}

__global__ void normalize_mask(const void* __restrict__ m)
{
    const int i = blockIdx.x * 256 + threadIdx.x;
    if (i >= MROW) return;
    const int mode = g_mask_mode;
    unsigned char r;
    if (mode == 1)      r = (((const unsigned char*)m)[i] != 0);
    else if (mode == 2) r = (((const float*)m)[i] != 0.0f);
    else                r = (((const int*)m)[i] != 0);
    g_mask[i] = r;
}

// ---------------- tf32-round copy (weights) ----------------
__global__ void __launch_bounds__(256)
round_copy(const float* __restrict__ s, float* __restrict__ d, int n4)
{
    const int i = blockIdx.x * 256 + threadIdx.x;
    if (i >= n4) return;
    float4 v = ((const float4*)s)[i];
    v.x = roundtf(v.x); v.y = roundtf(v.y); v.z = roundtf(v.z); v.w = roundtf(v.w);
    ((float4*)d)[i] = v;
}

// =====================================================================
// TF32 GEMM (mma.sync + ldmatrix):  C[M,N] = A[M,K]*W[N,K]^T + bias[N]
// A, W pre-rounded to tf32-representable f32.
// CTA tile 256x128, 256 thr (8 warps 4x2), warp tile 64x64.
// 4-stage cp.async ring; ldmatrix.x4 fragment loads; XOR-swizzled smem.
// Requires M%256==0, N%128==0, K%16==0 (all shapes satisfy).
// mode 0: C=acc+bias ; 1: C=roundtf(relu(acc+bias)) ;
// mode 2: C=acc+bias+addm, Cr=roundtf(C)
//
// smem per stage: A 256 rows x 64B (16KB) + B 128 rows x 64B (8KB) = 24KB.
// Row r, 16B k-chunk g stored at chunk position g ^ ((r>>1)&3).
// =====================================================================
#define STG_BYTES 24576
#define GEMM_DSMEM (4*STG_BYTES + 1024)

__device__ __forceinline__ void load_stage(const float* __restrict__ A,
                                           const float* __restrict__ W,
                                           int K, int bm0, int bn0, int kt,
                                           char* stg, int tid)
{
    const float* Asrc = A + (size_t)bm0 * K + kt * 16;
    const float* Wsrc = W + (size_t)bn0 * K + kt * 16;
#pragma unroll
    for (int i = 0; i < 4; i++) {
        const int idx = i * 256 + tid;        // 0..1023
        const int row = idx >> 2;             // 0..255
        const int g   = idx & 3;
        const int perm = g ^ ((row >> 1) & 3);
        cp16(stg + row * 64 + perm * 16, Asrc + (size_t)row * K + g * 4);
    }
#pragma unroll
    for (int i = 0; i < 2; i++) {
        const int idx = i * 256 + tid;        // 0..511
        const int row = idx >> 2;             // 0..127
        const int g   = idx & 3;
        const int perm = g ^ ((row >> 1) & 3);
        cp16(stg + 16384 + row * 64 + perm * 16, Wsrc + (size_t)row * K + g * 4);
    }
    asm volatile("cp.async.commit_group;" ::: "memory");
}

__global__ void __launch_bounds__(256)
gemm_tf32(const float* __restrict__ A, const float* __restrict__ W,
          const float* __restrict__ bias, const float* __restrict__ addm,
          float* __restrict__ C, float* __restrict__ Cr,
          int M, int N, int K, int mode)
{
    extern __shared__ char smraw[];
    char* base = (char*)(((uintptr_t)smraw + 1023) & ~(uintptr_t)1023);
    const uint32_t sb = smem_u32(base);

    const int tid  = threadIdx.x;
    const int lane = tid & 31;
    const int warp = tid >> 5;
    const int wm   = warp >> 1;          // 0..3
    const int wn   = warp & 1;           // 0..1
    const int gid  = lane >> 2;
    const int tg   = lane & 3;
    const int mtx  = lane >> 3;          // 0..3 (ldmatrix matrix id)
    const int rowin = lane & 7;

    const int bm0 = blockIdx.y * 256;
    const int bn0 = blockIdx.x * 128;

    // precompute stage-relative ldmatrix addresses
    uint32_t offA[2][4], offB[2][4];
#pragma unroll
    for (int ks = 0; ks < 2; ks++) {
#pragma unroll
        for (int mi = 0; mi < 4; mi++) {
            const int r = wm * 64 + mi * 16 + (mtx & 1) * 8 + rowin;
            const int g = ks * 2 + (mtx >> 1);
            offA[ks][mi] = (uint32_t)(r * 64 + ((g ^ ((r >> 1) & 3)) << 4));
        }
#pragma unroll
        for (int p = 0; p < 4; p++) {
            const int r = wn * 64 + p * 16 + ((mtx >> 1) & 1) * 8 + rowin;
            const int g = ks * 2 + (mtx & 1);
            offB[ks][p] = (uint32_t)(16384 + r * 64 + ((g ^ ((r >> 1) & 3)) << 4));
        }
    }

    float acc[4][8][4];
#pragma unroll
    for (int mi = 0; mi < 4; mi++)
#pragma unroll
        for (int nj = 0; nj < 8; nj++)
#pragma unroll
            for (int c = 0; c < 4; c++) acc[mi][nj][c] = 0.f;

    const int nkt = K >> 4;

    // prologue: prefetch 3 stages
    load_stage(A, W, K, bm0, bn0, 0, base,                 tid);
    load_stage(A, W, K, bm0, bn0, 1, base + STG_BYTES,     tid);
    load_stage(A, W, K, bm0, bn0, 2, base + 2 * STG_BYTES, tid);

    for (int kt = 0; kt < nkt; kt++) {
        asm volatile("cp.async.wait_group 2;" ::: "memory");
        __syncthreads();

        const uint32_t stg = sb + (uint32_t)(kt & 3) * STG_BYTES;

#pragma unroll
        for (int ks = 0; ks < 2; ks++) {
            uint32_t a[4][4], b[8][2];
#pragma unroll
            for (int mi = 0; mi < 4; mi++)
                ldsm4(a[mi][0], a[mi][1], a[mi][2], a[mi][3], stg + offA[ks][mi]);
#pragma unroll
            for (int p = 0; p < 4; p++) {
                uint32_t d0, d1, d2, d3;
                ldsm4(d0, d1, d2, d3, stg + offB[ks][p]);
                b[2 * p][0] = d0; b[2 * p][1] = d1;
                b[2 * p + 1][0] = d2; b[2 * p + 1][1] = d3;
            }
#pragma unroll
            for (int nj = 0; nj < 8; nj++) {
#pragma unroll
                for (int mi = 0; mi < 4; mi++) {
                    asm volatile(
                        "mma.sync.aligned.m16n8k8.row.col.f32.tf32.tf32.f32 "
                        "{%0,%1,%2,%3},{%4,%5,%6,%7},{%8,%9},{%0,%1,%2,%3};\n"
                        : "+f"(acc[mi][nj][0]), "+f"(acc[mi][nj][1]),
                          "+f"(acc[mi][nj][2]), "+f"(acc[mi][nj][3])
                        : "r"(a[mi][0]), "r"(a[mi][1]), "r"(a[mi][2]), "r"(a[mi][3]),
                          "r"(b[nj][0]), "r"(b[nj][1]));
                }
            }
        }

        if (kt + 3 < nkt)
            load_stage(A, W, K, bm0, bn0, kt + 3, base + (size_t)((kt + 3) & 3) * STG_BYTES, tid);
        else
            asm volatile("cp.async.commit_group;" ::: "memory");
    }

    // epilogue: direct reg -> gmem float2 stores
#pragma unroll
    for (int mi = 0; mi < 4; mi++) {
#pragma unroll
        for (int nj = 0; nj < 8; nj++) {
            const int col = bn0 + wn * 64 + nj * 8 + tg * 2;
            const float2 bv = *(const float2*)&bias[col];
#pragma unroll
            for (int ch = 0; ch < 2; ch++) {
                const int row = bm0 + wm * 64 + mi * 16 + gid + ch * 8;
                float x0 = acc[mi][nj][ch * 2 + 0] + bv.x;
                float x1 = acc[mi][nj][ch * 2 + 1] + bv.y;
                const size_t gofs = (size_t)row * N + col;
                if (mode == 1) {
                    x0 = roundtf(fmaxf(x0, 0.f));
                    x1 = roundtf(fmaxf(x1, 0.f));
                } else if (mode == 2) {
                    const float2 av = *(const float2*)&addm[gofs];
                    x0 += av.x; x1 += av.y;
                    float2 rr; rr.x = roundtf(x0); rr.y = roundtf(x1);
                    *(float2*)&Cr[gofs] = rr;
                }
                float2 o; o.x = x0; o.y = x1;
                *(float2*)&C[gofs] = o;
            }
        }
    }
}

// =====================================================================
// Row LayerNorm over first 2048 cols + optional tail passthrough.
// =====================================================================
__global__ void __launch_bounds__(256)
ln_rows(const float* __restrict__ in, float* __restrict__ out,
        const float* __restrict__ g, const float* __restrict__ b,
        const float* __restrict__ tail_src,
        int in_stride, int out_stride, int tail_stride, int tail_len,
        int round_out)
{
    const int row = blockIdx.x;
    const int tid = threadIdx.x;
    const float* x = in + (size_t)row * in_stride;

    const float4 va = *(const float4*)&x[tid * 4];
    const float4 vb = *(const float4*)&x[(tid + 256) * 4];

    double s  = (double)va.x + va.y + va.z + va.w + (double)vb.x + vb.y + vb.z + vb.w;
    double ss = (double)va.x * va.x + (double)va.y * va.y + (double)va.z * va.z + (double)va.w * va.w
              + (double)vb.x * vb.x + (double)vb.y * vb.y + (double)vb.z * vb.z + (double)vb.w * vb.w;

#pragma unroll
    for (int off = 16; off; off >>= 1) {
        s  += __shfl_down_sync(0xffffffffu, s, off);
        ss += __shfl_down_sync(0xffffffffu, ss, off);
    }
    __shared__ double rs[8], rss[8];
    __shared__ float s_mean, s_rstd;
    const int warp = tid >> 5, lane = tid & 31;
    if (lane == 0) { rs[warp] = s; rss[warp] = ss; }
    __syncthreads();
    if (tid == 0) {
        double S = 0.0, SQ = 0.0;
        for (int w = 0; w < 8; w++) { S += rs[w]; SQ += rss[w]; }
        const double mean = S / 2048.0;
        const double var  = SQ / 2048.0 - mean * mean;
        s_mean = (float)mean;
        s_rstd = (float)(1.0 / sqrt(var + 1e-5));
    }
    __syncthreads();
    const float mean = s_mean, rstd = s_rstd;

    float* o = out + (size_t)row * out_stride;
    {
        const int c0 = tid * 4;
        const float4 g4 = *(const float4*)&g[c0];
        const float4 b4 = *(const float4*)&b[c0];
        float4 r;
        r.x = (va.x - mean) * rstd * g4.x + b4.x;
        r.y = (va.y - mean) * rstd * g4.y + b4.y;
        r.z = (va.z - mean) * rstd * g4.z + b4.z;
        r.w = (va.w - mean) * rstd * g4.w + b4.w;
        if (round_out) { r.x = roundtf(r.x); r.y = roundtf(r.y); r.z = roundtf(r.z); r.w = roundtf(r.w); }
        *(float4*)&o[c0] = r;
    }
    {
        const int c1 = (tid + 256) * 4;
        const float4 g4 = *(const float4*)&g[c1];
        const float4 b4 = *(const float4*)&b[c1];
        float4 r;
        r.x = (vb.x - mean) * rstd * g4.x + b4.x;
        r.y = (vb.y - mean) * rstd * g4.y + b4.y;
        r.z = (vb.z - mean) * rstd * g4.z + b4.z;
        r.w = (vb.w - mean) * rstd * g4.w + b4.w;
        if (round_out) { r.x = roundtf(r.x); r.y = roundtf(r.y); r.z = roundtf(r.z); r.w = roundtf(r.w); }
        *(float4*)&o[c1] = r;
    }
    if (tail_len) {
        for (int c = tid; c < tail_len; c += 256) {
            float t = tail_src[(size_t)row * tail_stride + 2048 + c];
            o[2048 + c] = round_out ? roundtf(t) : t;
        }
    }
}

// =====================================================================
// Attention: one CTA per batch; softmax over SLOT axis per pano column.
// =====================================================================
#define ATT 384
__global__ void __launch_bounds__(ATT)
attn_kernel(const float* __restrict__ q, const float* __restrict__ k,
            const float* __restrict__ v, const unsigned char* __restrict__ mask,
            float* __restrict__ updates, float* __restrict__ attn_out)
{
    const int b = blockIdx.x;
    const int tid = threadIdx.x;

    __shared__ float qs[10][65];
    __shared__ float ks[36][65];
    __shared__ float dots[10][37];
    __shared__ float attns[10][37];

    const int i = tid / 36;
    const int j = tid % 36;
    float acc = 0.f;

    for (int d0 = 0; d0 < DD; d0 += 64) {
        for (int t = tid; t < 640; t += ATT) {
            const int r = t >> 6, c = t & 63;
            qs[r][c] = q[(size_t)(b * 10 + r) * DD + d0 + c];
        }
        for (int t = tid; t < 2304; t += ATT) {
            const int r = t >> 6, c = t & 63;
            ks[r][c] = k[(size_t)(b * 36 + r) * DD + d0 + c];
        }
        __syncthreads();
        if (tid < 360) {
#pragma unroll 16
            for (int dd = 0; dd < 64; dd++)
                acc += qs[i][dd] * ks[j][dd];
        }
        __syncthreads();
    }
    if (tid < 360) dots[i][j] = acc;
    __syncthreads();

    if (tid < 36) {
        const float scale = rsqrtf(2176.0f);
        const int jj = tid;
        bool m[10];
        float dv[10];
        float mx = -3.402823466e38f;
#pragma unroll
        for (int ii = 0; ii < 10; ii++) {
            m[ii] = (mask[b * 10 + ii] != 0);
            dv[ii] = dots[ii][jj] * scale;
            if (!m[ii]) mx = fmaxf(mx, dv[ii]);
        }
        float e[10], sum = 0.f;
#pragma unroll
        for (int ii = 0; ii < 10; ii++) {
            e[ii] = m[ii] ? 0.f : expf(dv[ii] - mx);
            sum += e[ii];
        }
        const float inv = 1.f / sum;
#pragma unroll
        for (int ii = 0; ii < 10; ii++) {
            const float a = e[ii] * inv;
            attns[ii][jj] = a;
            attn_out[(size_t)(b * 10 + ii) * 36 + jj] = a;
        }
    }
    __syncthreads();

    for (int d = tid; d < DD; d += ATT) {
        float u[10];
#pragma unroll
        for (int ii = 0; ii < 10; ii++) u[ii] = 0.f;
        for (int jj = 0; jj < 36; jj++) {
            const float vv = v[(size_t)(b * 36 + jj) * DD + d];
#pragma unroll
            for (int ii = 0; ii < 10; ii++) u[ii] += attns[ii][jj] * vv;
        }
#pragma unroll
        for (int ii = 0; ii < 10; ii++)
            updates[(size_t)(b * 10 + ii) * DD + d] = roundtf(u[ii]);
    }
}

// ---------------- GRU elementwise ----------------
__global__ void __launch_bounds__(256)
gru_kernel(const float* __restrict__ gi, const float* __restrict__ gh,
           const float* __restrict__ h, float* __restrict__ hnew)
{
    const size_t idx = (size_t)blockIdx.x * 256 + threadIdx.x;
    const size_t row = idx >> 11;
    const size_t f   = idx & 2047;
    const size_t gb  = row * (size_t)F3 + f;
    const float ir = gi[gb], iz = gi[gb + 2048], in_ = gi[gb + 4096];
    const float hr = gh[gb], hz = gh[gb + 2048], hn  = gh[gb + 4096];
    const float r = 1.f / (1.f + expf(-(ir + hr)));
    const float z = 1.f / (1.f + expf(-(iz + hz)));
    const float n = tanhf(in_ + r * hn);
    hnew[idx] = (1.f - z) * n + z * h[idx];
}

// ---------------- misc copies ----------------
__global__ void __launch_bounds__(256)
init_h(const float* __restrict__ cand, float* __restrict__ h, float* __restrict__ hr)
{
    const size_t idx = (size_t)blockIdx.x * 256 + threadIdx.x;
    const size_t row = idx >> 11;
    const size_t f   = idx & 2047;
    const float x = cand[row * (size_t)DD + f];
    h[idx]  = x;
    hr[idx] = roundtf(x);
}

__global__ void __launch_bounds__(256)
write_slots(const float* __restrict__ h, const float* __restrict__ cand,
            float* __restrict__ out)
{
    const size_t idx = (size_t)blockIdx.x * 256 + threadIdx.x;
    const size_t row = idx / DD;
    const size_t c   = idx % DD;
    out[idx] = (c < 2048) ? h[row * (size_t)FF + c] : cand[idx];
}

// =====================================================================
// launch
// =====================================================================
extern "C" void kernel_launch(void* const* d_in, const int* in_sizes, int n_in,
                              void* d_out, int out_size)
{
    const float* cand  = (const float*)d_in[0];
    const float* pano  = (const float*)d_in[1];
    const void*  maskp = d_in[2];
    const float* Wq = (const float*)d_in[3];  const float* bq = (const float*)d_in[4];
    const float* Wk = (const float*)d_in[5];  const float* bk = (const float*)d_in[6];
    const float* Wv = (const float*)d_in[7];  const float* bv = (const float*)d_in[8];
    const float* W_ih = (const float*)d_in[9];  const float* b_ih = (const float*)d_in[10];
    const float* W_hh = (const float*)d_in[11]; const float* b_hh = (const float*)d_in[12];
    const float* W1 = (const float*)d_in[13]; const float* b1 = (const float*)d_in[14];
    const float* W2 = (const float*)d_in[15]; const float* b2 = (const float*)d_in[16];
    const float* ln_in_g = (const float*)d_in[17]; const float* ln_in_b = (const float*)d_in[18];
    const float* ln_sl_g = (const float*)d_in[19]; const float* ln_sl_b = (const float*)d_in[20];
    const float* ln_pr_g = (const float*)d_in[21]; const float* ln_pr_b = (const float*)d_in[22];

    float* out      = (float*)d_out;
    float* out_attn = out + (size_t)MROW * DD;

    float *p_pano, *p_k, *p_v, *p_s, *p_q, *p_upd, *p_t1, *p_gi, *p_gh;
    float *p_h, *p_hr, *p_hnew, *p_pre, *p_w;
    unsigned char* p_mask;
    cudaGetSymbolAddress((void**)&p_pano, g_pano_ln);
    cudaGetSymbolAddress((void**)&p_k,    g_k);
    cudaGetSymbolAddress((void**)&p_v,    g_v);
    cudaGetSymbolAddress((void**)&p_s,    g_s);
    cudaGetSymbolAddress((void**)&p_q,    g_q);
    cudaGetSymbolAddress((void**)&p_upd,  g_upd);
    cudaGetSymbolAddress((void**)&p_t1,   g_t1);
    cudaGetSymbolAddress((void**)&p_gi,   g_gi);
    cudaGetSymbolAddress((void**)&p_gh,   g_gh);
    cudaGetSymbolAddress((void**)&p_h,    g_h);
    cudaGetSymbolAddress((void**)&p_hr,   g_hr);
    cudaGetSymbolAddress((void**)&p_hnew, g_hnew);
    cudaGetSymbolAddress((void**)&p_pre,  g_pre);
    cudaGetSymbolAddress((void**)&p_w,    g_wtf);
    cudaGetSymbolAddress((void**)&p_mask, g_mask);

    cudaFuncSetAttribute(gemm_tf32, cudaFuncAttributeMaxDynamicSharedMemorySize, GEMM_DSMEM);

    // rounded weight copies
    float* rWq = p_w;
    float* rWk = rWq + SZ_QKV;
    float* rWv = rWk + SZ_QKV;
    float* rWih = rWv + SZ_QKV;
    float* rWhh = rWih + SZ_IH;
    float* rW1  = rWhh + SZ_HH;
    float* rW2  = rW1 + SZ_W1;
    round_copy<<<(SZ_QKV/4 + 255)/256, 256>>>(Wq, rWq, SZ_QKV/4);
    round_copy<<<(SZ_QKV/4 + 255)/256, 256>>>(Wk, rWk, SZ_QKV/4);
    round_copy<<<(SZ_QKV/4 + 255)/256, 256>>>(Wv, rWv, SZ_QKV/4);
    round_copy<<<(SZ_IH /4 + 255)/256, 256>>>(W_ih, rWih, SZ_IH/4);
    round_copy<<<(SZ_HH /4 + 255)/256, 256>>>(W_hh, rWhh, SZ_HH/4);
    round_copy<<<(SZ_W1 /4 + 255)/256, 256>>>(W1, rW1, SZ_W1/4);
    round_copy<<<(SZ_W2 /4 + 255)/256, 256>>>(W2, rW2, SZ_W2/4);

    // mask dtype detection + canonicalization
    detect_mask<<<1, 256>>>((const unsigned char*)maskp);
    normalize_mask<<<(MROW + 255) / 256, 256>>>(maskp);

    // pano LN (rounded; consumed only as GEMM A for k/v)
    ln_rows<<<PROW, 256>>>(pano, p_pano, ln_in_g, ln_in_b, pano, DD, DD, DD, DD - FF, 1);

    // k, v projections
    {
        dim3 grd(DD / 128, PROW / 256);
        gemm_tf32<<<grd, 256, GEMM_DSMEM>>>(p_pano, rWk, bk, nullptr, p_k, nullptr, PROW, DD, DD, 0);
        gemm_tf32<<<grd, 256, GEMM_DSMEM>>>(p_pano, rWv, bv, nullptr, p_v, nullptr, PROW, DD, DD, 0);
    }

    // h0 = cand[..., :F] (exact + rounded shadow)
    init_h<<<(MROW * FF) / 256, 256>>>(cand, p_h, p_hr);

    for (int it = 0; it < 3; it++) {
        ln_rows<<<MROW, 256>>>(p_h, p_s, ln_sl_g, ln_sl_b, cand, FF, DD, DD, DD - FF, 1);
        {
            dim3 grd(DD / 128, MROW / 256);
            gemm_tf32<<<grd, 256, GEMM_DSMEM>>>(p_s, rWq, bq, nullptr, p_q, nullptr, MROW, DD, DD, 0);
        }
        attn_kernel<<<BB, ATT>>>(p_q, p_k, p_v, p_mask, p_upd, out_attn);
        {
            dim3 grd(F3 / 128, MROW / 256);
            gemm_tf32<<<grd, 256, GEMM_DSMEM>>>(p_upd, rWih, b_ih, nullptr, p_gi, nullptr, MROW, F3, DD, 0);
            gemm_tf32<<<grd, 256, GEMM_DSMEM>>>(p_hr,  rWhh, b_hh, nullptr, p_gh, nullptr, MROW, F3, FF, 0);
        }
        gru_kernel<<<(MROW * FF) / 256, 256>>>(p_gi, p_gh, p_h, p_hnew);
        ln_rows<<<MROW, 256>>>(p_hnew, p_pre, ln_pr_g, ln_pr_b, nullptr, FF, FF, 0, 0, 1);
        {
            dim3 grd(HH / 128, MROW / 256);
            gemm_tf32<<<grd, 256, GEMM_DSMEM>>>(p_pre, rW1, b1, nullptr, p_t1, nullptr, MROW, HH, FF, 1);
        }
        {
            dim3 grd(FF / 128, MROW / 256);
            gemm_tf32<<<grd, 256, GEMM_DSMEM>>>(p_t1, rW2, b2, p_hnew, p_h, p_hr, MROW, FF, HH, 2);
        }
    }

    // slots output = concat(h, angle)
    write_slots<<<(MROW * DD) / 256, 256>>>(p_h, cand, out);
}

// round 6
// speedup vs baseline: 1.6730x; 1.2908x over previous
#include <cuda_runtime.h>
#include <cstdint>
#include <cstddef>

// ---------------- problem constants ----------------
#define BB   1024
#define SS   10
#define NN   36
#define FF   2048
#define DD   2176
#define HH   2176
#define F3   6144
#define MROW (BB*SS)          // 10240
#define PROW (BB*NN)          // 36864

#define SZ_QKV (2176*2176)
#define SZ_IH  (6144*2176)
#define SZ_HH  (6144*2048)
#define SZ_W1  (2176*2048)
#define SZ_W2  (2048*2176)

// ---------------- scratch (device globals; no allocation allowed) --------
__device__ float g_pano_ln[(size_t)PROW * DD];
__device__ float g_k      [(size_t)PROW * DD];
__device__ float g_v      [(size_t)PROW * DD];
__device__ float g_s      [(size_t)MROW * DD];
__device__ float g_q      [(size_t)MROW * DD];
__device__ float g_upd    [(size_t)MROW * DD];
__device__ float g_t1     [(size_t)MROW * HH];
__device__ float g_gi     [(size_t)MROW * F3];
__device__ float g_gh     [(size_t)MROW * F3];
__device__ float g_h      [(size_t)MROW * FF];
__device__ float g_hr     [(size_t)MROW * FF];   // tf32-rounded copy of h
__device__ float g_hnew   [(size_t)MROW * FF];
__device__ float g_pre    [(size_t)MROW * FF];
__device__ float g_wtf    [(size_t)3*SZ_QKV + SZ_IH + SZ_HH + SZ_W1 + SZ_W2];
__device__ int            g_mask_mode;
__device__ unsigned char  g_mask[MROW];

// ---------------- helpers ----------------
__device__ __forceinline__ float roundtf(float x) {
    uint32_t r;
    asm("cvt.rna.tf32.f32 %0, %1;" : "=r"(r) : "f"(x));
    return __uint_as_float(r);
}

__device__ __forceinline__ void cp16(void* dst, const float* src) {
    uint32_t d = (uint32_t)__cvta_generic_to_shared(dst);
    asm volatile("cp.async.cg.shared.global [%0], [%1], 16;" :: "r"(d), "l"(src));
}

__device__ __forceinline__ uint32_t smem_u32(const void* p) {
    uint32_t a;
    asm("{ .reg .u64 t; cvta.to.shared.u64 t, %1; cvt.u32.u64 %0, t; }" : "=r"(a) : "l"(p));
    return a;
}

__device__ __forceinline__ void ldsm4(uint32_t& d0, uint32_t& d1, uint32_t& d2,
                                      uint32_t& d3, uint32_t addr) {
    asm volatile("ldmatrix.sync.aligned.m8n8.x4.shared.b16 {%0,%1,%2,%3}, [%4];"
                 : "=r"(d0), "=r"(d1), "=r"(d2), "=r"(d3) : "r"(addr));
}

// =====================================================================
// Mask dtype detection + normalization (bool widened to unknown dtype).
// =====================================================================
__global__ void detect_mask(const unsigned char* __restrict__ m)
{
    __shared__ int has1, has23;
    if (threadIdx.x == 0) { has1 = 0; has23 = 0; }
    __syncthreads();
    for (int i = threadIdx.x; i < MROW; i += 256) {
        if (m[i]) {
            const int p = i & 3;
            if (p == 1) atomicOr(&has1, 1);
            if (p >= 2) atomicOr(&has23, 1);
        }
    }
    __syncthreads();
    if (threadIdx.x == 0)
        g_mask_mode = has1 ? 1 : (has23 ? 2 : 0);
}

__global__ void normalize_mask(const void* __restrict__ m)
{
    const int i = blockIdx.x * 256 + threadIdx.x;
    if (i >= MROW) return;
    const int mode = g_mask_mode;
    unsigned char r;
    if (mode == 1)      r = (((const unsigned char*)m)[i] != 0);
    else if (mode == 2) r = (((const float*)m)[i] != 0.0f);
    else                r = (((const int*)m)[i] != 0);
    g_mask[i] = r;
}

// ---------------- tf32-round copy (weights) ----------------
__global__ void __launch_bounds__(256)
round_copy(const float* __restrict__ s, float* __restrict__ d, int n4)
{
    const int i = blockIdx.x * 256 + threadIdx.x;
    if (i >= n4) return;
    float4 v = ((const float4*)s)[i];
    v.x = roundtf(v.x); v.y = roundtf(v.y); v.z = roundtf(v.z); v.w = roundtf(v.w);
    ((float4*)d)[i] = v;
}

// =====================================================================
// TF32 GEMM (mma.sync + ldmatrix, software-pipelined fragments)
// C[M,N] = A[M,K]*W[N,K]^T + bias[N]; A,W pre-rounded tf32 grid.
// CTA 256x128, 8 warps (4x2), warp 64x64. 4-stage cp.async ring.
// Fragment double-buffer: LDSM for (ks+1) overlaps 64 MMAs of (ks).
// mode 0: +bias ; 1: roundtf(relu(+bias)) ; 2: +bias+addm, Cr=roundtf
// =====================================================================
#define STG_BYTES 24576
#define GEMM_DSMEM (4*STG_BYTES + 1024)

__device__ __forceinline__ void load_stage(const float* __restrict__ A,
                                           const float* __restrict__ W,
                                           int K, int bm0, int bn0, int kt,
                                           char* stg, int tid)
{
    const float* Asrc = A + (size_t)bm0 * K + kt * 16;
    const float* Wsrc = W + (size_t)bn0 * K + kt * 16;
#pragma unroll
    for (int i = 0; i < 4; i++) {
        const int idx = i * 256 + tid;        // 0..1023
        const int row = idx >> 2;             // 0..255
        const int g   = idx & 3;
        const int perm = g ^ ((row >> 1) & 3);
        cp16(stg + row * 64 + perm * 16, Asrc + (size_t)row * K + g * 4);
    }
#pragma unroll
    for (int i = 0; i < 2; i++) {
        const int idx = i * 256 + tid;        // 0..511
        const int row = idx >> 2;             // 0..127
        const int g   = idx & 3;
        const int perm = g ^ ((row >> 1) & 3);
        cp16(stg + 16384 + row * 64 + perm * 16, Wsrc + (size_t)row * K + g * 4);
    }
    asm volatile("cp.async.commit_group;" ::: "memory");
}

__device__ __forceinline__ void load_frags(uint32_t stg, const uint32_t* oA,
                                           const uint32_t* oB,
                                           uint32_t a[4][4], uint32_t b[8][2])
{
#pragma unroll
    for (int mi = 0; mi < 4; mi++)
        ldsm4(a[mi][0], a[mi][1], a[mi][2], a[mi][3], stg + oA[mi]);
#pragma unroll
    for (int p = 0; p < 4; p++) {
        uint32_t d0, d1, d2, d3;
        ldsm4(d0, d1, d2, d3, stg + oB[p]);
        b[2 * p][0] = d0;     b[2 * p][1] = d1;
        b[2 * p + 1][0] = d2; b[2 * p + 1][1] = d3;
    }
}

__device__ __forceinline__ void do_mmas(const uint32_t a[4][4], const uint32_t b[8][2],
                                        float acc[4][8][4])
{
#pragma unroll
    for (int nj = 0; nj < 8; nj++) {
#pragma unroll
        for (int mi = 0; mi < 4; mi++) {
            asm volatile(
                "mma.sync.aligned.m16n8k8.row.col.f32.tf32.tf32.f32 "
                "{%0,%1,%2,%3},{%4,%5,%6,%7},{%8,%9},{%0,%1,%2,%3};\n"
                : "+f"(acc[mi][nj][0]), "+f"(acc[mi][nj][1]),
                  "+f"(acc[mi][nj][2]), "+f"(acc[mi][nj][3])
                : "r"(a[mi][0]), "r"(a[mi][1]), "r"(a[mi][2]), "r"(a[mi][3]),
                  "r"(b[nj][0]), "r"(b[nj][1]));
        }
    }
}

__global__ void __launch_bounds__(256)
gemm_tf32(const float* __restrict__ A, const float* __restrict__ W,
          const float* __restrict__ bias, const float* __restrict__ addm,
          float* __restrict__ C, float* __restrict__ Cr,
          int M, int N, int K, int mode)
{
    extern __shared__ char smraw[];
    char* base = (char*)(((uintptr_t)smraw + 1023) & ~(uintptr_t)1023);
    const uint32_t sb = smem_u32(base);

    const int tid  = threadIdx.x;
    const int lane = tid & 31;
    const int warp = tid >> 5;
    const int wm   = warp >> 1;          // 0..3
    const int wn   = warp & 1;           // 0..1
    const int gid  = lane >> 2;
    const int tg   = lane & 3;
    const int mtx  = lane >> 3;          // 0..3 (ldmatrix matrix id)
    const int rowin = lane & 7;

    const int bm0 = blockIdx.y * 256;
    const int bn0 = blockIdx.x * 128;

    // stage-relative ldmatrix addresses per ks
    uint32_t offA[2][4], offB[2][4];
#pragma unroll
    for (int ks = 0; ks < 2; ks++) {
#pragma unroll
        for (int mi = 0; mi < 4; mi++) {
            const int r = wm * 64 + mi * 16 + (mtx & 1) * 8 + rowin;
            const int g = ks * 2 + (mtx >> 1);
            offA[ks][mi] = (uint32_t)(r * 64 + ((g ^ ((r >> 1) & 3)) << 4));
        }
#pragma unroll
        for (int p = 0; p < 4; p++) {
            const int r = wn * 64 + p * 16 + ((mtx >> 1) & 1) * 8 + rowin;
            const int g = ks * 2 + (mtx & 1);
            offB[ks][p] = (uint32_t)(16384 + r * 64 + ((g ^ ((r >> 1) & 3)) << 4));
        }
    }

    float acc[4][8][4];
#pragma unroll
    for (int mi = 0; mi < 4; mi++)
#pragma unroll
        for (int nj = 0; nj < 8; nj++)
#pragma unroll
            for (int c = 0; c < 4; c++) acc[mi][nj][c] = 0.f;

    const int nkt = K >> 4;

    // prologue: prefetch 3 stages
    load_stage(A, W, K, bm0, bn0, 0, base,                 tid);
    load_stage(A, W, K, bm0, bn0, 1, base + STG_BYTES,     tid);
    load_stage(A, W, K, bm0, bn0, 2, base + 2 * STG_BYTES, tid);
    asm volatile("cp.async.wait_group 2;" ::: "memory");
    __syncthreads();

    uint32_t fa[2][4][4], fb[2][8][2];
    load_frags(sb, offA[0], offB[0], fa[0], fb[0]);

    for (int kt = 0; kt < nkt; kt++) {
        const uint32_t stg_cur = sb + (uint32_t)(kt & 3) * STG_BYTES;

        // ---- step 0: producer for kt+3, prefetch (kt, ks1), MMA (kt, ks0)
        if (kt + 3 < nkt)
            load_stage(A, W, K, bm0, bn0, kt + 3,
                       base + (size_t)((kt + 3) & 3) * STG_BYTES, tid);
        else
            asm volatile("cp.async.commit_group;" ::: "memory");

        load_frags(stg_cur, offA[1], offB[1], fa[1], fb[1]);
        do_mmas(fa[0], fb[0], acc);

        // ---- step 1: advance stage, prefetch (kt+1, ks0), MMA (kt, ks1)
        asm volatile("cp.async.wait_group 2;" ::: "memory");
        __syncthreads();

        if (kt + 1 < nkt) {
            const uint32_t stg_nxt = sb + (uint32_t)((kt + 1) & 3) * STG_BYTES;
            load_frags(stg_nxt, offA[0], offB[0], fa[0], fb[0]);
        }
        do_mmas(fa[1], fb[1], acc);
    }

    // epilogue: direct reg -> gmem float2 stores
#pragma unroll
    for (int mi = 0; mi < 4; mi++) {
#pragma unroll
        for (int nj = 0; nj < 8; nj++) {
            const int col = bn0 + wn * 64 + nj * 8 + tg * 2;
            const float2 bv = *(const float2*)&bias[col];
#pragma unroll
            for (int ch = 0; ch < 2; ch++) {
                const int row = bm0 + wm * 64 + mi * 16 + gid + ch * 8;
                float x0 = acc[mi][nj][ch * 2 + 0] + bv.x;
                float x1 = acc[mi][nj][ch * 2 + 1] + bv.y;
                const size_t gofs = (size_t)row * N + col;
                if (mode == 1) {
                    x0 = roundtf(fmaxf(x0, 0.f));
                    x1 = roundtf(fmaxf(x1, 0.f));
                } else if (mode == 2) {
                    const float2 av = *(const float2*)&addm[gofs];
                    x0 += av.x; x1 += av.y;
                    float2 rr; rr.x = roundtf(x0); rr.y = roundtf(x1);
                    *(float2*)&Cr[gofs] = rr;
                }
                float2 o; o.x = x0; o.y = x1;
                *(float2*)&C[gofs] = o;
            }
        }
    }
}

// =====================================================================
// Row LayerNorm over first 2048 cols + optional tail passthrough.
// =====================================================================
__global__ void __launch_bounds__(256)
ln_rows(const float* __restrict__ in, float* __restrict__ out,
        const float* __restrict__ g, const float* __restrict__ b,
        const float* __restrict__ tail_src,
        int in_stride, int out_stride, int tail_stride, int tail_len,
        int round_out)
{
    const int row = blockIdx.x;
    const int tid = threadIdx.x;
    const float* x = in + (size_t)row * in_stride;

    const float4 va = *(const float4*)&x[tid * 4];
    const float4 vb = *(const float4*)&x[(tid + 256) * 4];

    double s  = (double)va.x + va.y + va.z + va.w + (double)vb.x + vb.y + vb.z + vb.w;
    double ss = (double)va.x * va.x + (double)va.y * va.y + (double)va.z * va.z + (double)va.w * va.w
              + (double)vb.x * vb.x + (double)vb.y * vb.y + (double)vb.z * vb.z + (double)vb.w * vb.w;

#pragma unroll
    for (int off = 16; off; off >>= 1) {
        s  += __shfl_down_sync(0xffffffffu, s, off);
        ss += __shfl_down_sync(0xffffffffu, ss, off);
    }
    __shared__ double rs[8], rss[8];
    __shared__ float s_mean, s_rstd;
    const int warp = tid >> 5, lane = tid & 31;
    if (lane == 0) { rs[warp] = s; rss[warp] = ss; }
    __syncthreads();
    if (tid == 0) {
        double S = 0.0, SQ = 0.0;
        for (int w = 0; w < 8; w++) { S += rs[w]; SQ += rss[w]; }
        const double mean = S / 2048.0;
        const double var  = SQ / 2048.0 - mean * mean;
        s_mean = (float)mean;
        s_rstd = (float)(1.0 / sqrt(var + 1e-5));
    }
    __syncthreads();
    const float mean = s_mean, rstd = s_rstd;

    float* o = out + (size_t)row * out_stride;
    {
        const int c0 = tid * 4;
        const float4 g4 = *(const float4*)&g[c0];
        const float4 b4 = *(const float4*)&b[c0];
        float4 r;
        r.x = (va.x - mean) * rstd * g4.x + b4.x;
        r.y = (va.y - mean) * rstd * g4.y + b4.y;
        r.z = (va.z - mean) * rstd * g4.z + b4.z;
        r.w = (va.w - mean) * rstd * g4.w + b4.w;
        if (round_out) { r.x = roundtf(r.x); r.y = roundtf(r.y); r.z = roundtf(r.z); r.w = roundtf(r.w); }
        *(float4*)&o[c0] = r;
    }
    {
        const int c1 = (tid + 256) * 4;
        const float4 g4 = *(const float4*)&g[c1];
        const float4 b4 = *(const float4*)&b[c1];
        float4 r;
        r.x = (vb.x - mean) * rstd * g4.x + b4.x;
        r.y = (vb.y - mean) * rstd * g4.y + b4.y;
        r.z = (vb.z - mean) * rstd * g4.z + b4.z;
        r.w = (vb.w - mean) * rstd * g4.w + b4.w;
        if (round_out) { r.x = roundtf(r.x); r.y = roundtf(r.y); r.z = roundtf(r.z); r.w = roundtf(r.w); }
        *(float4*)&o[c1] = r;
    }
    if (tail_len) {
        for (int c = tid; c < tail_len; c += 256) {
            float t = tail_src[(size_t)row * tail_stride + 2048 + c];
            o[2048 + c] = round_out ? roundtf(t) : t;
        }
    }
}

// =====================================================================
// Attention: one CTA per batch; softmax over SLOT axis per pano column.
// =====================================================================
#define ATT 384
__global__ void __launch_bounds__(ATT)
attn_kernel(const float* __restrict__ q, const float* __restrict__ k,
            const float* __restrict__ v, const unsigned char* __restrict__ mask,
            float* __restrict__ updates, float* __restrict__ attn_out)
{
    const int b = blockIdx.x;
    const int tid = threadIdx.x;

    __shared__ float qs[10][65];
    __shared__ float ks[36][65];
    __shared__ float dots[10][37];
    __shared__ float attns[10][37];

    const int i = tid / 36;
    const int j = tid % 36;
    float acc = 0.f;

    for (int d0 = 0; d0 < DD; d0 += 64) {
        for (int t = tid; t < 640; t += ATT) {
            const int r = t >> 6, c = t & 63;
            qs[r][c] = q[(size_t)(b * 10 + r) * DD + d0 + c];
        }
        for (int t = tid; t < 2304; t += ATT) {
            const int r = t >> 6, c = t & 63;
            ks[r][c] = k[(size_t)(b * 36 + r) * DD + d0 + c];
        }
        __syncthreads();
        if (tid < 360) {
#pragma unroll 16
            for (int dd = 0; dd < 64; dd++)
                acc += qs[i][dd] * ks[j][dd];
        }
        __syncthreads();
    }
    if (tid < 360) dots[i][j] = acc;
    __syncthreads();

    if (tid < 36) {
        const float scale = rsqrtf(2176.0f);
        const int jj = tid;
        bool m[10];
        float dv[10];
        float mx = -3.402823466e38f;
#pragma unroll
        for (int ii = 0; ii < 10; ii++) {
            m[ii] = (mask[b * 10 + ii] != 0);
            dv[ii] = dots[ii][jj] * scale;
            if (!m[ii]) mx = fmaxf(mx, dv[ii]);
        }
        float e[10], sum = 0.f;
#pragma unroll
        for (int ii = 0; ii < 10; ii++) {
            e[ii] = m[ii] ? 0.f : expf(dv[ii] - mx);
            sum += e[ii];
        }
        const float inv = 1.f / sum;
#pragma unroll
        for (int ii = 0; ii < 10; ii++) {
            const float a = e[ii] * inv;
            attns[ii][jj] = a;
            attn_out[(size_t)(b * 10 + ii) * 36 + jj] = a;
        }
    }
    __syncthreads();

    for (int d = tid; d < DD; d += ATT) {
        float u[10];
#pragma unroll
        for (int ii = 0; ii < 10; ii++) u[ii] = 0.f;
        for (int jj = 0; jj < 36; jj++) {
            const float vv = v[(size_t)(b * 36 + jj) * DD + d];
#pragma unroll
            for (int ii = 0; ii < 10; ii++) u[ii] += attns[ii][jj] * vv;
        }
#pragma unroll
        for (int ii = 0; ii < 10; ii++)
            updates[(size_t)(b * 10 + ii) * DD + d] = roundtf(u[ii]);
    }
}

// ---------------- GRU elementwise ----------------
__global__ void __launch_bounds__(256)
gru_kernel(const float* __restrict__ gi, const float* __restrict__ gh,
           const float* __restrict__ h, float* __restrict__ hnew)
{
    const size_t idx = (size_t)blockIdx.x * 256 + threadIdx.x;
    const size_t row = idx >> 11;
    const size_t f   = idx & 2047;
    const size_t gb  = row * (size_t)F3 + f;
    const float ir = gi[gb], iz = gi[gb + 2048], in_ = gi[gb + 4096];
    const float hr = gh[gb], hz = gh[gb + 2048], hn  = gh[gb + 4096];
    const float r = 1.f / (1.f + expf(-(ir + hr)));
    const float z = 1.f / (1.f + expf(-(iz + hz)));
    const float n = tanhf(in_ + r * hn);
    hnew[idx] = (1.f - z) * n + z * h[idx];
}

// ---------------- misc copies ----------------
__global__ void __launch_bounds__(256)
init_h(const float* __restrict__ cand, float* __restrict__ h, float* __restrict__ hr)
{
    const size_t idx = (size_t)blockIdx.x * 256 + threadIdx.x;
    const size_t row = idx >> 11;
    const size_t f   = idx & 2047;
    const float x = cand[row * (size_t)DD + f];
    h[idx]  = x;
    hr[idx] = roundtf(x);
}

__global__ void __launch_bounds__(256)
write_slots(const float* __restrict__ h, const float* __restrict__ cand,
            float* __restrict__ out)
{
    const size_t idx = (size_t)blockIdx.x * 256 + threadIdx.x;
    const size_t row = idx / DD;
    const size_t c   = idx % DD;
    out[idx] = (c < 2048) ? h[row * (size_t)FF + c] : cand[idx];
}

// =====================================================================
// launch
// =====================================================================
extern "C" void kernel_launch(void* const* d_in, const int* in_sizes, int n_in,
                              void* d_out, int out_size)
{
    const float* cand  = (const float*)d_in[0];
    const float* pano  = (const float*)d_in[1];
    const void*  maskp = d_in[2];
    const float* Wq = (const float*)d_in[3];  const float* bq = (const float*)d_in[4];
    const float* Wk = (const float*)d_in[5];  const float* bk = (const float*)d_in[6];
    const float* Wv = (const float*)d_in[7];  const float* bv = (const float*)d_in[8];
    const float* W_ih = (const float*)d_in[9];  const float* b_ih = (const float*)d_in[10];
    const float* W_hh = (const float*)d_in[11]; const float* b_hh = (const float*)d_in[12];
    const float* W1 = (const float*)d_in[13]; const float* b1 = (const float*)d_in[14];
    const float* W2 = (const float*)d_in[15]; const float* b2 = (const float*)d_in[16];
    const float* ln_in_g = (const float*)d_in[17]; const float* ln_in_b = (const float*)d_in[18];
    const float* ln_sl_g = (const float*)d_in[19]; const float* ln_sl_b = (const float*)d_in[20];
    const float* ln_pr_g = (const float*)d_in[21]; const float* ln_pr_b = (const float*)d_in[22];

    float* out      = (float*)d_out;
    float* out_attn = out + (size_t)MROW * DD;

    float *p_pano, *p_k, *p_v, *p_s, *p_q, *p_upd, *p_t1, *p_gi, *p_gh;
    float *p_h, *p_hr, *p_hnew, *p_pre, *p_w;
    unsigned char* p_mask;
    cudaGetSymbolAddress((void**)&p_pano, g_pano_ln);
    cudaGetSymbolAddress((void**)&p_k,    g_k);
    cudaGetSymbolAddress((void**)&p_v,    g_v);
    cudaGetSymbolAddress((void**)&p_s,    g_s);
    cudaGetSymbolAddress((void**)&p_q,    g_q);
    cudaGetSymbolAddress((void**)&p_upd,  g_upd);
    cudaGetSymbolAddress((void**)&p_t1,   g_t1);
    cudaGetSymbolAddress((void**)&p_gi,   g_gi);
    cudaGetSymbolAddress((void**)&p_gh,   g_gh);
    cudaGetSymbolAddress((void**)&p_h,    g_h);
    cudaGetSymbolAddress((void**)&p_hr,   g_hr);
    cudaGetSymbolAddress((void**)&p_hnew, g_hnew);
    cudaGetSymbolAddress((void**)&p_pre,  g_pre);
    cudaGetSymbolAddress((void**)&p_w,    g_wtf);
    cudaGetSymbolAddress((void**)&p_mask, g_mask);

    cudaFuncSetAttribute(gemm_tf32, cudaFuncAttributeMaxDynamicSharedMemorySize, GEMM_DSMEM);

    // rounded weight copies
    float* rWq = p_w;
    float* rWk = rWq + SZ_QKV;
    float* rWv = rWk + SZ_QKV;
    float* rWih = rWv + SZ_QKV;
    float* rWhh = rWih + SZ_IH;
    float* rW1  = rWhh + SZ_HH;
    float* rW2  = rW1 + SZ_W1;
    round_copy<<<(SZ_QKV/4 + 255)/256, 256>>>(Wq, rWq, SZ_QKV/4);
    round_copy<<<(SZ_QKV/4 + 255)/256, 256>>>(Wk, rWk, SZ_QKV/4);
    round_copy<<<(SZ_QKV/4 + 255)/256, 256>>>(Wv, rWv, SZ_QKV/4);
    round_copy<<<(SZ_IH /4 + 255)/256, 256>>>(W_ih, rWih, SZ_IH/4);
    round_copy<<<(SZ_HH /4 + 255)/256, 256>>>(W_hh, rWhh, SZ_HH/4);
    round_copy<<<(SZ_W1 /4 + 255)/256, 256>>>(W1, rW1, SZ_W1/4);
    round_copy<<<(SZ_W2 /4 + 255)/256, 256>>>(W2, rW2, SZ_W2/4);

    // mask dtype detection + canonicalization
    detect_mask<<<1, 256>>>((const unsigned char*)maskp);
    normalize_mask<<<(MROW + 255) / 256, 256>>>(maskp);

    // pano LN (rounded; consumed only as GEMM A for k/v)
    ln_rows<<<PROW, 256>>>(pano, p_pano, ln_in_g, ln_in_b, pano, DD, DD, DD, DD - FF, 1);

    // k, v projections
    {
        dim3 grd(DD / 128, PROW / 256);
        gemm_tf32<<<grd, 256, GEMM_DSMEM>>>(p_pano, rWk, bk, nullptr, p_k, nullptr, PROW, DD, DD, 0);
        gemm_tf32<<<grd, 256, GEMM_DSMEM>>>(p_pano, rWv, bv, nullptr, p_v, nullptr, PROW, DD, DD, 0);
    }

    // h0 = cand[..., :F] (exact + rounded shadow)
    init_h<<<(MROW * FF) / 256, 256>>>(cand, p_h, p_hr);

    for (int it = 0; it < 3; it++) {
        ln_rows<<<MROW, 256>>>(p_h, p_s, ln_sl_g, ln_sl_b, cand, FF, DD, DD, DD - FF, 1);
        {
            dim3 grd(DD / 128, MROW / 256);
            gemm_tf32<<<grd, 256, GEMM_DSMEM>>>(p_s, rWq, bq, nullptr, p_q, nullptr, MROW, DD, DD, 0);
        }
        attn_kernel<<<BB, ATT>>>(p_q, p_k, p_v, p_mask, p_upd, out_attn);
        {
            dim3 grd(F3 / 128, MROW / 256);
            gemm_tf32<<<grd, 256, GEMM_DSMEM>>>(p_upd, rWih, b_ih, nullptr, p_gi, nullptr, MROW, F3, DD, 0);
            gemm_tf32<<<grd, 256, GEMM_DSMEM>>>(p_hr,  rWhh, b_hh, nullptr, p_gh, nullptr, MROW, F3, FF, 0);
        }
        gru_kernel<<<(MROW * FF) / 256, 256>>>(p_gi, p_gh, p_h, p_hnew);
        ln_rows<<<MROW, 256>>>(p_hnew, p_pre, ln_pr_g, ln_pr_b, nullptr, FF, FF, 0, 0, 1);
        {
            dim3 grd(HH / 128, MROW / 256);
            gemm_tf32<<<grd, 256, GEMM_DSMEM>>>(p_pre, rW1, b1, nullptr, p_t1, nullptr, MROW, HH, FF, 1);
        }
        {
            dim3 grd(FF / 128, MROW / 256);
            gemm_tf32<<<grd, 256, GEMM_DSMEM>>>(p_t1, rW2, b2, p_hnew, p_h, p_hr, MROW, FF, HH, 2);
        }
    }

    // slots output = concat(h, angle)
    write_slots<<<(MROW * DD) / 256, 256>>>(p_h, cand, out);
}

// round 7
// speedup vs baseline: 2.4174x; 1.4450x over previous
#include <cuda_runtime.h>
#include <cuda_fp16.h>
#include <cstdint>
#include <cstddef>

// ---------------- problem constants ----------------
#define BB   1024
#define SS   10
#define NN   36
#define FF   2048
#define DD   2176
#define HH   2176
#define F3   6144
#define MROW (BB*SS)          // 10240
#define PROW (BB*NN)          // 36864

#define SZ_QKV (2176*2176)
#define SZ_IH  (6144*2176)
#define SZ_HH  (6144*2048)
#define SZ_W1  (2176*2048)
#define SZ_W2  (2048*2176)

// ---------------- scratch (device globals; no allocation allowed) --------
__device__ __half g_pano_ln[(size_t)PROW * DD];
__device__ float  g_k      [(size_t)PROW * DD];
__device__ float  g_v      [(size_t)PROW * DD];
__device__ __half g_s      [(size_t)MROW * DD];
__device__ float  g_q      [(size_t)MROW * DD];
__device__ __half g_upd    [(size_t)MROW * DD];
__device__ __half g_t1     [(size_t)MROW * HH];
__device__ float  g_gi     [(size_t)MROW * F3];
__device__ float  g_gh     [(size_t)MROW * F3];
__device__ float  g_h      [(size_t)MROW * FF];
__device__ __half g_hr     [(size_t)MROW * FF];   // fp16 copy of h
__device__ float  g_hnew   [(size_t)MROW * FF];
__device__ __half g_pre    [(size_t)MROW * FF];
__device__ __half g_wh     [(size_t)3*SZ_QKV + SZ_IH + SZ_HH + SZ_W1 + SZ_W2];
__device__ int            g_mask_mode;
__device__ unsigned char  g_mask[MROW];

// ---------------- helpers ----------------
__device__ __forceinline__ void cp16(void* dst, const void* src) {
    uint32_t d = (uint32_t)__cvta_generic_to_shared(dst);
    asm volatile("cp.async.cg.shared.global [%0], [%1], 16;" :: "r"(d), "l"(src));
}

__device__ __forceinline__ uint32_t smem_u32(const void* p) {
    uint32_t a;
    asm("{ .reg .u64 t; cvta.to.shared.u64 t, %1; cvt.u32.u64 %0, t; }" : "=r"(a) : "l"(p));
    return a;
}

__device__ __forceinline__ void ldsm4(uint32_t& d0, uint32_t& d1, uint32_t& d2,
                                      uint32_t& d3, uint32_t addr) {
    asm volatile("ldmatrix.sync.aligned.m8n8.x4.shared.b16 {%0,%1,%2,%3}, [%4];"
                 : "=r"(d0), "=r"(d1), "=r"(d2), "=r"(d3) : "r"(addr));
}

// =====================================================================
// Mask dtype detection + normalization (bool widened to unknown dtype).
// =====================================================================
__global__ void detect_mask(const unsigned char* __restrict__ m)
{
    __shared__ int has1, has23;
    if (threadIdx.x == 0) { has1 = 0; has23 = 0; }
    __syncthreads();
    for (int i = threadIdx.x; i < MROW; i += 256) {
        if (m[i]) {
            const int p = i & 3;
            if (p == 1) atomicOr(&has1, 1);
            if (p >= 2) atomicOr(&has23, 1);
        }
    }
    __syncthreads();
    if (threadIdx.x == 0)
        g_mask_mode = has1 ? 1 : (has23 ? 2 : 0);
}

__global__ void normalize_mask(const void* __restrict__ m)
{
    const int i = blockIdx.x * 256 + threadIdx.x;
    if (i >= MROW) return;
    const int mode = g_mask_mode;
    unsigned char r;
    if (mode == 1)      r = (((const unsigned char*)m)[i] != 0);
    else if (mode == 2) r = (((const float*)m)[i] != 0.0f);
    else                r = (((const int*)m)[i] != 0);
    g_mask[i] = r;
}

// ---------------- fp16 weight copy ----------------
__global__ void __launch_bounds__(256)
half_copy(const float* __restrict__ s, __half* __restrict__ d, int n4)
{
    const int i = blockIdx.x * 256 + threadIdx.x;
    if (i >= n4) return;
    const float4 v = ((const float4*)s)[i];
    __half2 h0 = __floats2half2_rn(v.x, v.y);
    __half2 h1 = __floats2half2_rn(v.z, v.w);
    uint2 o; o.x = *(uint32_t*)&h0; o.y = *(uint32_t*)&h1;
    ((uint2*)d)[i] = o;
}

// =====================================================================
// FP16 GEMM (mma.sync.m16n8k16 + ldmatrix, software-pipelined frags)
// C[M,N] = A[M,K]*W[N,K]^T + bias[N]; A,W are __half; acc fp32.
// CTA 256x128, 8 warps (4x2), warp 64x64. 4-stage cp.async ring,
// stage = k32 (row width 64B = 32 halfs), XOR-swizzled 16B chunks.
// mode 0: Cf(f32) = acc+bias
// mode 1: Ch(f16) = relu(acc+bias)
// mode 2: Cf(f32) = acc+bias+addm ; Ch(f16) = same value
// =====================================================================
#define STG_BYTES 24576
#define GEMM_DSMEM (4*STG_BYTES + 1024)

__device__ __forceinline__ void load_stage(const __half* __restrict__ A,
                                           const __half* __restrict__ W,
                                           int K, int bm0, int bn0, int kt,
                                           char* stg, int tid)
{
    const __half* Asrc = A + (size_t)bm0 * K + kt * 32;
    const __half* Wsrc = W + (size_t)bn0 * K + kt * 32;
#pragma unroll
    for (int i = 0; i < 4; i++) {
        const int idx = i * 256 + tid;        // 0..1023
        const int row = idx >> 2;             // 0..255
        const int g   = idx & 3;
        const int perm = g ^ ((row >> 1) & 3);
        cp16(stg + row * 64 + perm * 16, Asrc + (size_t)row * K + g * 8);
    }
#pragma unroll
    for (int i = 0; i < 2; i++) {
        const int idx = i * 256 + tid;        // 0..511
        const int row = idx >> 2;             // 0..127
        const int g   = idx & 3;
        const int perm = g ^ ((row >> 1) & 3);
        cp16(stg + 16384 + row * 64 + perm * 16, Wsrc + (size_t)row * K + g * 8);
    }
    asm volatile("cp.async.commit_group;" ::: "memory");
}

__device__ __forceinline__ void load_frags(uint32_t stg, const uint32_t* oA,
                                           const uint32_t* oB,
                                           uint32_t a[4][4], uint32_t b[8][2])
{
#pragma unroll
    for (int mi = 0; mi < 4; mi++)
        ldsm4(a[mi][0], a[mi][1], a[mi][2], a[mi][3], stg + oA[mi]);
#pragma unroll
    for (int p = 0; p < 4; p++) {
        uint32_t d0, d1, d2, d3;
        ldsm4(d0, d1, d2, d3, stg + oB[p]);
        // d0={n0-7,k0-7} d1={n8-15,k0-7} d2={n0-7,k8-15} d3={n8-15,k8-15}
        b[2 * p][0] = d0;     b[2 * p][1] = d2;
        b[2 * p + 1][0] = d1; b[2 * p + 1][1] = d3;
    }
}

__device__ __forceinline__ void do_mmas(const uint32_t a[4][4], const uint32_t b[8][2],
                                        float acc[4][8][4])
{
#pragma unroll
    for (int nj = 0; nj < 8; nj++) {
#pragma unroll
        for (int mi = 0; mi < 4; mi++) {
            asm volatile(
                "mma.sync.aligned.m16n8k16.row.col.f32.f16.f16.f32 "
                "{%0,%1,%2,%3},{%4,%5,%6,%7},{%8,%9},{%0,%1,%2,%3};\n"
                : "+f"(acc[mi][nj][0]), "+f"(acc[mi][nj][1]),
                  "+f"(acc[mi][nj][2]), "+f"(acc[mi][nj][3])
                : "r"(a[mi][0]), "r"(a[mi][1]), "r"(a[mi][2]), "r"(a[mi][3]),
                  "r"(b[nj][0]), "r"(b[nj][1]));
        }
    }
}

__global__ void __launch_bounds__(256)
gemm_fp16(const __half* __restrict__ A, const __half* __restrict__ W,
          const float* __restrict__ bias, const float* __restrict__ addm,
          float* __restrict__ Cf, __half* __restrict__ Ch,
          int M, int N, int K, int mode)
{
    extern __shared__ char smraw[];
    char* base = (char*)(((uintptr_t)smraw + 1023) & ~(uintptr_t)1023);
    const uint32_t sb = smem_u32(base);

    const int tid  = threadIdx.x;
    const int lane = tid & 31;
    const int warp = tid >> 5;
    const int wm   = warp >> 1;          // 0..3
    const int wn   = warp & 1;           // 0..1
    const int gid  = lane >> 2;
    const int tg   = lane & 3;
    const int mtx  = lane >> 3;          // 0..3 (ldmatrix matrix id)
    const int rowin = lane & 7;

    const int bm0 = blockIdx.y * 256;
    const int bn0 = blockIdx.x * 128;

    // stage-relative ldmatrix addresses per ks (ks = k16 half of k32 stage)
    uint32_t offA[2][4], offB[2][4];
#pragma unroll
    for (int ks = 0; ks < 2; ks++) {
#pragma unroll
        for (int mi = 0; mi < 4; mi++) {
            const int r = wm * 64 + mi * 16 + (mtx & 1) * 8 + rowin;
            const int g = ks * 2 + (mtx >> 1);
            offA[ks][mi] = (uint32_t)(r * 64 + ((g ^ ((r >> 1) & 3)) << 4));
        }
#pragma unroll
        for (int p = 0; p < 4; p++) {
            const int r = wn * 64 + p * 16 + (mtx & 1) * 8 + rowin;
            const int g = ks * 2 + (mtx >> 1);
            offB[ks][p] = (uint32_t)(16384 + r * 64 + ((g ^ ((r >> 1) & 3)) << 4));
        }
    }

    float acc[4][8][4];
#pragma unroll
    for (int mi = 0; mi < 4; mi++)
#pragma unroll
        for (int nj = 0; nj < 8; nj++)
#pragma unroll
            for (int c = 0; c < 4; c++) acc[mi][nj][c] = 0.f;

    const int nkt = K >> 5;

    // prologue: prefetch 3 stages
    load_stage(A, W, K, bm0, bn0, 0, base,                 tid);
    load_stage(A, W, K, bm0, bn0, 1, base + STG_BYTES,     tid);
    load_stage(A, W, K, bm0, bn0, 2, base + 2 * STG_BYTES, tid);
    asm volatile("cp.async.wait_group 2;" ::: "memory");
    __syncthreads();

    uint32_t fa[2][4][4], fb[2][8][2];
    load_frags(sb, offA[0], offB[0], fa[0], fb[0]);

    for (int kt = 0; kt < nkt; kt++) {
        const uint32_t stg_cur = sb + (uint32_t)(kt & 3) * STG_BYTES;

        // ---- step 0: producer for kt+3, prefetch (kt, ks1), MMA (kt, ks0)
        if (kt + 3 < nkt)
            load_stage(A, W, K, bm0, bn0, kt + 3,
                       base + (size_t)((kt + 3) & 3) * STG_BYTES, tid);
        else
            asm volatile("cp.async.commit_group;" ::: "memory");

        load_frags(stg_cur, offA[1], offB[1], fa[1], fb[1]);
        do_mmas(fa[0], fb[0], acc);

        // ---- step 1: advance stage, prefetch (kt+1, ks0), MMA (kt, ks1)
        asm volatile("cp.async.wait_group 2;" ::: "memory");
        __syncthreads();

        if (kt + 1 < nkt) {
            const uint32_t stg_nxt = sb + (uint32_t)((kt + 1) & 3) * STG_BYTES;
            load_frags(stg_nxt, offA[0], offB[0], fa[0], fb[0]);
        }
        do_mmas(fa[1], fb[1], acc);
    }

    // epilogue
#pragma unroll
    for (int mi = 0; mi < 4; mi++) {
#pragma unroll
        for (int nj = 0; nj < 8; nj++) {
            const int col = bn0 + wn * 64 + nj * 8 + tg * 2;
            const float2 bv = *(const float2*)&bias[col];
#pragma unroll
            for (int ch = 0; ch < 2; ch++) {
                const int row = bm0 + wm * 64 + mi * 16 + gid + ch * 8;
                float x0 = acc[mi][nj][ch * 2 + 0] + bv.x;
                float x1 = acc[mi][nj][ch * 2 + 1] + bv.y;
                const size_t gofs = (size_t)row * N + col;
                if (mode == 0) {
                    float2 o; o.x = x0; o.y = x1;
                    *(float2*)&Cf[gofs] = o;
                } else if (mode == 1) {
                    __half2 hh = __floats2half2_rn(fmaxf(x0, 0.f), fmaxf(x1, 0.f));
                    *(__half2*)&Ch[gofs] = hh;
                } else {
                    const float2 av = *(const float2*)&addm[gofs];
                    x0 += av.x; x1 += av.y;
                    float2 o; o.x = x0; o.y = x1;
                    *(float2*)&Cf[gofs] = o;
                    __half2 hh = __floats2half2_rn(x0, x1);
                    *(__half2*)&Ch[gofs] = hh;
                }
            }
        }
    }
}

// =====================================================================
// Row LayerNorm over first 2048 cols + tail passthrough. __half output.
// =====================================================================
__global__ void __launch_bounds__(256)
ln_rows(const float* __restrict__ in, __half* __restrict__ out,
        const float* __restrict__ g, const float* __restrict__ b,
        const float* __restrict__ tail_src,
        int in_stride, int out_stride, int tail_stride, int tail_len)
{
    const int row = blockIdx.x;
    const int tid = threadIdx.x;
    const float* x = in + (size_t)row * in_stride;

    const float4 va = *(const float4*)&x[tid * 4];
    const float4 vb = *(const float4*)&x[(tid + 256) * 4];

    double s  = (double)va.x + va.y + va.z + va.w + (double)vb.x + vb.y + vb.z + vb.w;
    double ss = (double)va.x * va.x + (double)va.y * va.y + (double)va.z * va.z + (double)va.w * va.w
              + (double)vb.x * vb.x + (double)vb.y * vb.y + (double)vb.z * vb.z + (double)vb.w * vb.w;

#pragma unroll
    for (int off = 16; off; off >>= 1) {
        s  += __shfl_down_sync(0xffffffffu, s, off);
        ss += __shfl_down_sync(0xffffffffu, ss, off);
    }
    __shared__ double rs[8], rss[8];
    __shared__ float s_mean, s_rstd;
    const int warp = tid >> 5, lane = tid & 31;
    if (lane == 0) { rs[warp] = s; rss[warp] = ss; }
    __syncthreads();
    if (tid == 0) {
        double S = 0.0, SQ = 0.0;
        for (int w = 0; w < 8; w++) { S += rs[w]; SQ += rss[w]; }
        const double mean = S / 2048.0;
        const double var  = SQ / 2048.0 - mean * mean;
        s_mean = (float)mean;
        s_rstd = (float)(1.0 / sqrt(var + 1e-5));
    }
    __syncthreads();
    const float mean = s_mean, rstd = s_rstd;

    __half* o = out + (size_t)row * out_stride;
    {
        const int c0 = tid * 4;
        const float4 g4 = *(const float4*)&g[c0];
        const float4 b4 = *(const float4*)&b[c0];
        __half2 h0 = __floats2half2_rn((va.x - mean) * rstd * g4.x + b4.x,
                                       (va.y - mean) * rstd * g4.y + b4.y);
        __half2 h1 = __floats2half2_rn((va.z - mean) * rstd * g4.z + b4.z,
                                       (va.w - mean) * rstd * g4.w + b4.w);
        *(__half2*)&o[c0]     = h0;
        *(__half2*)&o[c0 + 2] = h1;
    }
    {
        const int c1 = (tid + 256) * 4;
        const float4 g4 = *(const float4*)&g[c1];
        const float4 b4 = *(const float4*)&b[c1];
        __half2 h0 = __floats2half2_rn((vb.x - mean) * rstd * g4.x + b4.x,
                                       (vb.y - mean) * rstd * g4.y + b4.y);
        __half2 h1 = __floats2half2_rn((vb.z - mean) * rstd * g4.z + b4.z,
                                       (vb.w - mean) * rstd * g4.w + b4.w);
        *(__half2*)&o[c1]     = h0;
        *(__half2*)&o[c1 + 2] = h1;
    }
    if (tail_len) {
        for (int c = tid; c < tail_len; c += 256)
            o[2048 + c] = __float2half_rn(tail_src[(size_t)row * tail_stride + 2048 + c]);
    }
}

// =====================================================================
// Attention: one CTA per batch; softmax over SLOT axis per pano column.
// q,k,v fp32; updates written fp16 (GEMM-A input).
// =====================================================================
#define ATT 384
__global__ void __launch_bounds__(ATT)
attn_kernel(const float* __restrict__ q, const float* __restrict__ k,
            const float* __restrict__ v, const unsigned char* __restrict__ mask,
            __half* __restrict__ updates, float* __restrict__ attn_out)
{
    const int b = blockIdx.x;
    const int tid = threadIdx.x;

    __shared__ float qs[10][65];
    __shared__ float ks[36][65];
    __shared__ float dots[10][37];
    __shared__ float attns[10][37];

    const int i = tid / 36;
    const int j = tid % 36;
    float acc = 0.f;

    for (int d0 = 0; d0 < DD; d0 += 64) {
        for (int t = tid; t < 640; t += ATT) {
            const int r = t >> 6, c = t & 63;
            qs[r][c] = q[(size_t)(b * 10 + r) * DD + d0 + c];
        }
        for (int t = tid; t < 2304; t += ATT) {
            const int r = t >> 6, c = t & 63;
            ks[r][c] = k[(size_t)(b * 36 + r) * DD + d0 + c];
        }
        __syncthreads();
        if (tid < 360) {
#pragma unroll 16
            for (int dd = 0; dd < 64; dd++)
                acc += qs[i][dd] * ks[j][dd];
        }
        __syncthreads();
    }
    if (tid < 360) dots[i][j] = acc;
    __syncthreads();

    if (tid < 36) {
        const float scale = rsqrtf(2176.0f);
        const int jj = tid;
        bool m[10];
        float dv[10];
        float mx = -3.402823466e38f;
#pragma unroll
        for (int ii = 0; ii < 10; ii++) {
            m[ii] = (mask[b * 10 + ii] != 0);
            dv[ii] = dots[ii][jj] * scale;
            if (!m[ii]) mx = fmaxf(mx, dv[ii]);
        }
        float e[10], sum = 0.f;
#pragma unroll
        for (int ii = 0; ii < 10; ii++) {
            e[ii] = m[ii] ? 0.f : expf(dv[ii] - mx);
            sum += e[ii];
        }
        const float inv = 1.f / sum;
#pragma unroll
        for (int ii = 0; ii < 10; ii++) {
            const float a = e[ii] * inv;
            attns[ii][jj] = a;
            attn_out[(size_t)(b * 10 + ii) * 36 + jj] = a;
        }
    }
    __syncthreads();

    for (int d = tid; d < DD; d += ATT) {
        float u[10];
#pragma unroll
        for (int ii = 0; ii < 10; ii++) u[ii] = 0.f;
        for (int jj = 0; jj < 36; jj++) {
            const float vv = v[(size_t)(b * 36 + jj) * DD + d];
#pragma unroll
            for (int ii = 0; ii < 10; ii++) u[ii] += attns[ii][jj] * vv;
        }
#pragma unroll
        for (int ii = 0; ii < 10; ii++)
            updates[(size_t)(b * 10 + ii) * DD + d] = __float2half_rn(u[ii]);
    }
}

// ---------------- GRU elementwise ----------------
__global__ void __launch_bounds__(256)
gru_kernel(const float* __restrict__ gi, const float* __restrict__ gh,
           const float* __restrict__ h, float* __restrict__ hnew)
{
    const size_t idx = (size_t)blockIdx.x * 256 + threadIdx.x;
    const size_t row = idx >> 11;
    const size_t f   = idx & 2047;
    const size_t gb  = row * (size_t)F3 + f;
    const float ir = gi[gb], iz = gi[gb + 2048], in_ = gi[gb + 4096];
    const float hr = gh[gb], hz = gh[gb + 2048], hn  = gh[gb + 4096];
    const float r = 1.f / (1.f + expf(-(ir + hr)));
    const float z = 1.f / (1.f + expf(-(iz + hz)));
    const float n = tanhf(in_ + r * hn);
    hnew[idx] = (1.f - z) * n + z * h[idx];
}

// ---------------- misc copies ----------------
__global__ void __launch_bounds__(256)
init_h(const float* __restrict__ cand, float* __restrict__ h, __half* __restrict__ hr)
{
    const size_t idx = (size_t)blockIdx.x * 256 + threadIdx.x;
    const size_t row = idx >> 11;
    const size_t f   = idx & 2047;
    const float x = cand[row * (size_t)DD + f];
    h[idx]  = x;
    hr[idx] = __float2half_rn(x);
}

__global__ void __launch_bounds__(256)
write_slots(const float* __restrict__ h, const float* __restrict__ cand,
            float* __restrict__ out)
{
    const size_t idx = (size_t)blockIdx.x * 256 + threadIdx.x;
    const size_t row = idx / DD;
    const size_t c   = idx % DD;
    out[idx] = (c < 2048) ? h[row * (size_t)FF + c] : cand[idx];
}

// =====================================================================
// launch
// =====================================================================
extern "C" void kernel_launch(void* const* d_in, const int* in_sizes, int n_in,
                              void* d_out, int out_size)
{
    const float* cand  = (const float*)d_in[0];
    const float* pano  = (const float*)d_in[1];
    const void*  maskp = d_in[2];
    const float* Wq = (const float*)d_in[3];  const float* bq = (const float*)d_in[4];
    const float* Wk = (const float*)d_in[5];  const float* bk = (const float*)d_in[6];
    const float* Wv = (const float*)d_in[7];  const float* bv = (const float*)d_in[8];
    const float* W_ih = (const float*)d_in[9];  const float* b_ih = (const float*)d_in[10];
    const float* W_hh = (const float*)d_in[11]; const float* b_hh = (const float*)d_in[12];
    const float* W1 = (const float*)d_in[13]; const float* b1 = (const float*)d_in[14];
    const float* W2 = (const float*)d_in[15]; const float* b2 = (const float*)d_in[16];
    const float* ln_in_g = (const float*)d_in[17]; const float* ln_in_b = (const float*)d_in[18];
    const float* ln_sl_g = (const float*)d_in[19]; const float* ln_sl_b = (const float*)d_in[20];
    const float* ln_pr_g = (const float*)d_in[21]; const float* ln_pr_b = (const float*)d_in[22];

    float* out      = (float*)d_out;
    float* out_attn = out + (size_t)MROW * DD;

    __half *p_pano, *p_s, *p_upd, *p_t1, *p_hr, *p_pre, *p_w;
    float *p_k, *p_v, *p_q, *p_gi, *p_gh, *p_h, *p_hnew;
    unsigned char* p_mask;
    cudaGetSymbolAddress((void**)&p_pano, g_pano_ln);
    cudaGetSymbolAddress((void**)&p_k,    g_k);
    cudaGetSymbolAddress((void**)&p_v,    g_v);
    cudaGetSymbolAddress((void**)&p_s,    g_s);
    cudaGetSymbolAddress((void**)&p_q,    g_q);
    cudaGetSymbolAddress((void**)&p_upd,  g_upd);
    cudaGetSymbolAddress((void**)&p_t1,   g_t1);
    cudaGetSymbolAddress((void**)&p_gi,   g_gi);
    cudaGetSymbolAddress((void**)&p_gh,   g_gh);
    cudaGetSymbolAddress((void**)&p_h,    g_h);
    cudaGetSymbolAddress((void**)&p_hr,   g_hr);
    cudaGetSymbolAddress((void**)&p_hnew, g_hnew);
    cudaGetSymbolAddress((void**)&p_pre,  g_pre);
    cudaGetSymbolAddress((void**)&p_w,    g_wh);
    cudaGetSymbolAddress((void**)&p_mask, g_mask);

    cudaFuncSetAttribute(gemm_fp16, cudaFuncAttributeMaxDynamicSharedMemorySize, GEMM_DSMEM);

    // fp16 weight copies
    __half* rWq = p_w;
    __half* rWk = rWq + SZ_QKV;
    __half* rWv = rWk + SZ_QKV;
    __half* rWih = rWv + SZ_QKV;
    __half* rWhh = rWih + SZ_IH;
    __half* rW1  = rWhh + SZ_HH;
    __half* rW2  = rW1 + SZ_W1;
    half_copy<<<(SZ_QKV/4 + 255)/256, 256>>>(Wq, rWq, SZ_QKV/4);
    half_copy<<<(SZ_QKV/4 + 255)/256, 256>>>(Wk, rWk, SZ_QKV/4);
    half_copy<<<(SZ_QKV/4 + 255)/256, 256>>>(Wv, rWv, SZ_QKV/4);
    half_copy<<<(SZ_IH /4 + 255)/256, 256>>>(W_ih, rWih, SZ_IH/4);
    half_copy<<<(SZ_HH /4 + 255)/256, 256>>>(W_hh, rWhh, SZ_HH/4);
    half_copy<<<(SZ_W1 /4 + 255)/256, 256>>>(W1, rW1, SZ_W1/4);
    half_copy<<<(SZ_W2 /4 + 255)/256, 256>>>(W2, rW2, SZ_W2/4);

    // mask dtype detection + canonicalization
    detect_mask<<<1, 256>>>((const unsigned char*)maskp);
    normalize_mask<<<(MROW + 255) / 256, 256>>>(maskp);

    // pano LN (fp16 out; consumed only as GEMM A for k/v)
    ln_rows<<<PROW, 256>>>(pano, p_pano, ln_in_g, ln_in_b, pano, DD, DD, DD, DD - FF);

    // k, v projections
    {
        dim3 grd(DD / 128, PROW / 256);
        gemm_fp16<<<grd, 256, GEMM_DSMEM>>>(p_pano, rWk, bk, nullptr, p_k, nullptr, PROW, DD, DD, 0);
        gemm_fp16<<<grd, 256, GEMM_DSMEM>>>(p_pano, rWv, bv, nullptr, p_v, nullptr, PROW, DD, DD, 0);
    }

    // h0 = cand[..., :F] (f32 + fp16 shadow)
    init_h<<<(MROW * FF) / 256, 256>>>(cand, p_h, p_hr);

    for (int it = 0; it < 3; it++) {
        ln_rows<<<MROW, 256>>>(p_h, p_s, ln_sl_g, ln_sl_b, cand, FF, DD, DD, DD - FF);
        {
            dim3 grd(DD / 128, MROW / 256);
            gemm_fp16<<<grd, 256, GEMM_DSMEM>>>(p_s, rWq, bq, nullptr, p_q, nullptr, MROW, DD, DD, 0);
        }
        attn_kernel<<<BB, ATT>>>(p_q, p_k, p_v, p_mask, p_upd, out_attn);
        {
            dim3 grd(F3 / 128, MROW / 256);
            gemm_fp16<<<grd, 256, GEMM_DSMEM>>>(p_upd, rWih, b_ih, nullptr, p_gi, nullptr, MROW, F3, DD, 0);
            gemm_fp16<<<grd, 256, GEMM_DSMEM>>>(p_hr,  rWhh, b_hh, nullptr, p_gh, nullptr, MROW, F3, FF, 0);
        }
        gru_kernel<<<(MROW * FF) / 256, 256>>>(p_gi, p_gh, p_h, p_hnew);
        ln_rows<<<MROW, 256>>>(p_hnew, p_pre, ln_pr_g, ln_pr_b, nullptr, FF, FF, 0, 0);
        {
            dim3 grd(HH / 128, MROW / 256);
            gemm_fp16<<<grd, 256, GEMM_DSMEM>>>(p_pre, rW1, b1, nullptr, nullptr, p_t1, MROW, HH, FF, 1);
        }
        {
            dim3 grd(FF / 128, MROW / 256);
            gemm_fp16<<<grd, 256, GEMM_DSMEM>>>(p_t1, rW2, b2, p_hnew, p_h, p_hr, MROW, FF, HH, 2);
        }
    }

    // slots output = concat(h, angle)
    write_slots<<<(MROW * DD) / 256, 256>>>(p_h, cand, out);
}

// round 8
// speedup vs baseline: 2.6447x; 1.0940x over previous
#include <cuda_runtime.h>
#include <cuda_fp16.h>
#include <cstdint>
#include <cstddef>

// ---------------- problem constants ----------------
#define BB   1024
#define SS   10
#define NN   36
#define FF   2048
#define DD   2176
#define HH   2176
#define F3   6144
#define MROW (BB*SS)          // 10240
#define PROW (BB*NN)          // 36864

#define SZ_QKV (2176*2176)
#define SZ_IH  (6144*2176)
#define SZ_HH  (6144*2048)
#define SZ_W1  (2176*2048)
#define SZ_W2  (2048*2176)
#define SZ_TOT ((size_t)3*SZ_QKV + SZ_IH + SZ_HH + SZ_W1 + SZ_W2)

// ---------------- scratch (device globals; no allocation allowed) --------
__device__ __half g_pano_ln[(size_t)PROW * DD];
__device__ float  g_k      [(size_t)PROW * DD];
__device__ float  g_v      [(size_t)PROW * DD];
__device__ __half g_s      [(size_t)MROW * DD];
__device__ float  g_q      [(size_t)MROW * DD];
__device__ __half g_upd    [(size_t)MROW * DD];
__device__ __half g_t1     [(size_t)MROW * HH];
__device__ float  g_gi     [(size_t)MROW * F3];
__device__ float  g_gh     [(size_t)MROW * F3];
__device__ float  g_h      [(size_t)MROW * FF];
__device__ __half g_hr     [(size_t)MROW * FF];
__device__ float  g_hnew   [(size_t)MROW * FF];
__device__ __half g_pre    [(size_t)MROW * FF];
__device__ __half g_wh     [SZ_TOT];
__device__ int            g_mask_mode;
__device__ unsigned char  g_mask[MROW];

// ---------------- helpers ----------------
__device__ __forceinline__ void cp16(void* dst, const void* src) {
    uint32_t d = (uint32_t)__cvta_generic_to_shared(dst);
    asm volatile("cp.async.cg.shared.global [%0], [%1], 16;" :: "r"(d), "l"(src));
}

__device__ __forceinline__ uint32_t smem_u32(const void* p) {
    uint32_t a;
    asm("{ .reg .u64 t; cvta.to.shared.u64 t, %1; cvt.u32.u64 %0, t; }" : "=r"(a) : "l"(p));
    return a;
}

__device__ __forceinline__ void ldsm4(uint32_t& d0, uint32_t& d1, uint32_t& d2,
                                      uint32_t& d3, uint32_t addr) {
    asm volatile("ldmatrix.sync.aligned.m8n8.x4.shared.b16 {%0,%1,%2,%3}, [%4];"
                 : "=r"(d0), "=r"(d1), "=r"(d2), "=r"(d3) : "r"(addr));
}

// =====================================================================
// Mask dtype detection + normalization (bool widened to unknown dtype).
// =====================================================================
__global__ void detect_mask(const unsigned char* __restrict__ m)
{
    __shared__ int has1, has23;
    if (threadIdx.x == 0) { has1 = 0; has23 = 0; }
    __syncthreads();
    for (int i = threadIdx.x; i < MROW; i += 256) {
        if (m[i]) {
            const int p = i & 3;
            if (p == 1) atomicOr(&has1, 1);
            if (p >= 2) atomicOr(&has23, 1);
        }
    }
    __syncthreads();
    if (threadIdx.x == 0)
        g_mask_mode = has1 ? 1 : (has23 ? 2 : 0);
}

__global__ void normalize_mask(const void* __restrict__ m)
{
    const int i = blockIdx.x * 256 + threadIdx.x;
    if (i >= MROW) return;
    const int mode = g_mask_mode;
    unsigned char r;
    if (mode == 1)      r = (((const unsigned char*)m)[i] != 0);
    else if (mode == 2) r = (((const float*)m)[i] != 0.0f);
    else                r = (((const int*)m)[i] != 0);
    g_mask[i] = r;
}

// ---------------- fused fp16 weight copy (single launch) ----------------
__global__ void __launch_bounds__(256)
half_copy_all(const float* s0, const float* s1, const float* s2,
              const float* s3, const float* s4, const float* s5,
              const float* s6, __half* __restrict__ d)
{
    const size_t seg_end[7] = {
        (size_t)SZ_QKV, (size_t)2*SZ_QKV, (size_t)3*SZ_QKV,
        (size_t)3*SZ_QKV + SZ_IH,
        (size_t)3*SZ_QKV + SZ_IH + SZ_HH,
        (size_t)3*SZ_QKV + SZ_IH + SZ_HH + SZ_W1,
        SZ_TOT };
    const float* srcs[7] = { s0, s1, s2, s3, s4, s5, s6 };

    const size_t i4 = (size_t)blockIdx.x * 256 + threadIdx.x;
    const size_t e0 = i4 * 4;
    if (e0 >= SZ_TOT) return;

    int seg = 0;
    size_t base = 0;
#pragma unroll
    for (int k = 0; k < 7; k++) {
        if (e0 >= seg_end[k]) { seg = k + 1; base = seg_end[k]; }
    }
    const float4 v = *(const float4*)(srcs[seg] + (e0 - base));
    __half2 h0 = __floats2half2_rn(v.x, v.y);
    __half2 h1 = __floats2half2_rn(v.z, v.w);
    uint2 o; o.x = *(uint32_t*)&h0; o.y = *(uint32_t*)&h1;
    *(uint2*)(d + e0) = o;
}

// =====================================================================
// FP16 GEMM: CTA 128x128, 128 thr (4 warps 2x2, warp 64x64).
// 3-stage cp.async ring, stage = k64 (row 128B, SW128-style swizzle).
// Fragment double-buffer across 4 k16 steps per stage; acc fp32.
// mode 0: Cf(f32,ldC) = acc+bias
// mode 1: Ch(f16)     = relu(acc+bias)
// mode 2: Cf(f32,ldC) = acc+bias+addm[ldN] ; Ch(f16) = same value
// Requires M%128==0, N%128==0, K%64==0.
// =====================================================================
#define STG_BYTES 32768
#define GEMM_DSMEM (3*STG_BYTES + 1024)

__device__ __forceinline__ void load_stage(const __half* __restrict__ A,
                                           const __half* __restrict__ W,
                                           int K, int bm0, int bn0, int kt,
                                           char* stg, int tid)
{
    const __half* Asrc = A + (size_t)bm0 * K + kt * 64;
    const __half* Wsrc = W + (size_t)bn0 * K + kt * 64;
#pragma unroll
    for (int i = 0; i < 8; i++) {
        const int idx = i * 128 + tid;        // 0..1023
        const int row = idx >> 3;             // 0..127
        const int g   = idx & 7;
        const int perm = g ^ (row & 7);
        cp16(stg + row * 128 + perm * 16, Asrc + (size_t)row * K + g * 8);
    }
#pragma unroll
    for (int i = 0; i < 8; i++) {
        const int idx = i * 128 + tid;
        const int row = idx >> 3;
        const int g   = idx & 7;
        const int perm = g ^ (row & 7);
        cp16(stg + 16384 + row * 128 + perm * 16, Wsrc + (size_t)row * K + g * 8);
    }
    asm volatile("cp.async.commit_group;" ::: "memory");
}

__device__ __forceinline__ void load_frags(uint32_t stg, const uint32_t* oA,
                                           const uint32_t* oB,
                                           uint32_t a[4][4], uint32_t b[8][2])
{
#pragma unroll
    for (int mi = 0; mi < 4; mi++)
        ldsm4(a[mi][0], a[mi][1], a[mi][2], a[mi][3], stg + oA[mi]);
#pragma unroll
    for (int p = 0; p < 4; p++) {
        uint32_t d0, d1, d2, d3;
        ldsm4(d0, d1, d2, d3, stg + oB[p]);
        b[2 * p][0] = d0;     b[2 * p][1] = d2;
        b[2 * p + 1][0] = d1; b[2 * p + 1][1] = d3;
    }
}

__device__ __forceinline__ void do_mmas(const uint32_t a[4][4], const uint32_t b[8][2],
                                        float acc[4][8][4])
{
#pragma unroll
    for (int nj = 0; nj < 8; nj++) {
#pragma unroll
        for (int mi = 0; mi < 4; mi++) {
            asm volatile(
                "mma.sync.aligned.m16n8k16.row.col.f32.f16.f16.f32 "
                "{%0,%1,%2,%3},{%4,%5,%6,%7},{%8,%9},{%0,%1,%2,%3};\n"
                : "+f"(acc[mi][nj][0]), "+f"(acc[mi][nj][1]),
                  "+f"(acc[mi][nj][2]), "+f"(acc[mi][nj][3])
                : "r"(a[mi][0]), "r"(a[mi][1]), "r"(a[mi][2]), "r"(a[mi][3]),
                  "r"(b[nj][0]), "r"(b[nj][1]));
        }
    }
}

__global__ void __launch_bounds__(128, 2)
gemm_fp16(const __half* __restrict__ A, const __half* __restrict__ W,
          const float* __restrict__ bias, const float* __restrict__ addm,
          float* __restrict__ Cf, __half* __restrict__ Ch,
          int M, int N, int K, int ldC, int mode)
{
    extern __shared__ char smraw[];
    char* base = (char*)(((uintptr_t)smraw + 1023) & ~(uintptr_t)1023);
    const uint32_t sb = smem_u32(base);

    const int tid  = threadIdx.x;
    const int lane = tid & 31;
    const int warp = tid >> 5;
    const int wm   = warp >> 1;          // 0..1
    const int wn   = warp & 1;           // 0..1
    const int gid  = lane >> 2;
    const int tg   = lane & 3;
    const int mtx  = lane >> 3;          // 0..3
    const int rowin = lane & 7;

    const int bm0 = blockIdx.y * 128;
    const int bn0 = blockIdx.x * 128;

    // stage-relative ldmatrix addresses for 4 k16 steps of a k64 stage
    uint32_t offA[4][4], offB[4][4];
#pragma unroll
    for (int ks = 0; ks < 4; ks++) {
#pragma unroll
        for (int mi = 0; mi < 4; mi++) {
            const int r = wm * 64 + mi * 16 + (mtx & 1) * 8 + rowin;
            const int g = ks * 2 + (mtx >> 1);
            offA[ks][mi] = (uint32_t)(r * 128 + ((g ^ (r & 7)) << 4));
        }
#pragma unroll
        for (int p = 0; p < 4; p++) {
            const int r = wn * 64 + p * 16 + (mtx & 1) * 8 + rowin;
            const int g = ks * 2 + (mtx >> 1);
            offB[ks][p] = (uint32_t)(16384 + r * 128 + ((g ^ (r & 7)) << 4));
        }
    }

    float acc[4][8][4];
#pragma unroll
    for (int mi = 0; mi < 4; mi++)
#pragma unroll
        for (int nj = 0; nj < 8; nj++)
#pragma unroll
            for (int c = 0; c < 4; c++) acc[mi][nj][c] = 0.f;

    const int nkt = K >> 6;

    // prologue: prefetch 2 stages
    load_stage(A, W, K, bm0, bn0, 0, base,             tid);
    load_stage(A, W, K, bm0, bn0, 1, base + STG_BYTES, tid);
    asm volatile("cp.async.wait_group 1;" ::: "memory");
    __syncthreads();

    uint32_t fa[2][4][4], fb[2][8][2];
    load_frags(sb, offA[0], offB[0], fa[0], fb[0]);

    int stg_i = 0;
    for (int kt = 0; kt < nkt; kt++) {
        const uint32_t stg = sb + (uint32_t)stg_i * STG_BYTES;
        const int stg_n = (stg_i == 2) ? 0 : stg_i + 1;

        // ks=0: producer for kt+2, prefetch ks1, MMA ks0
        if (kt + 2 < nkt) {
            const int stg_p = (stg_n == 2) ? 0 : stg_n + 1;
            load_stage(A, W, K, bm0, bn0, kt + 2, base + stg_p * STG_BYTES, tid);
        } else {
            asm volatile("cp.async.commit_group;" ::: "memory");
        }
        load_frags(stg, offA[1], offB[1], fa[1], fb[1]);
        do_mmas(fa[0], fb[0], acc);

        // ks=1
        load_frags(stg, offA[2], offB[2], fa[0], fb[0]);
        do_mmas(fa[1], fb[1], acc);

        // ks=2
        load_frags(stg, offA[3], offB[3], fa[1], fb[1]);
        do_mmas(fa[0], fb[0], acc);

        // ks=3: stage advance
        asm volatile("cp.async.wait_group 1;" ::: "memory");
        __syncthreads();
        if (kt + 1 < nkt)
            load_frags(sb + (uint32_t)stg_n * STG_BYTES, offA[0], offB[0], fa[0], fb[0]);
        do_mmas(fa[1], fb[1], acc);

        stg_i = stg_n;
    }

    // epilogue
#pragma unroll
    for (int mi = 0; mi < 4; mi++) {
#pragma unroll
        for (int nj = 0; nj < 8; nj++) {
            const int col = bn0 + wn * 64 + nj * 8 + tg * 2;
            const float2 bv = *(const float2*)&bias[col];
#pragma unroll
            for (int ch = 0; ch < 2; ch++) {
                const int row = bm0 + wm * 64 + mi * 16 + gid + ch * 8;
                float x0 = acc[mi][nj][ch * 2 + 0] + bv.x;
                float x1 = acc[mi][nj][ch * 2 + 1] + bv.y;
                if (mode == 0) {
                    float2 o; o.x = x0; o.y = x1;
                    *(float2*)&Cf[(size_t)row * ldC + col] = o;
                } else if (mode == 1) {
                    __half2 hh = __floats2half2_rn(fmaxf(x0, 0.f), fmaxf(x1, 0.f));
                    *(__half2*)&Ch[(size_t)row * N + col] = hh;
                } else {
                    const float2 av = *(const float2*)&addm[(size_t)row * N + col];
                    x0 += av.x; x1 += av.y;
                    float2 o; o.x = x0; o.y = x1;
                    *(float2*)&Cf[(size_t)row * ldC + col] = o;
                    __half2 hh = __floats2half2_rn(x0, x1);
                    *(__half2*)&Ch[(size_t)row * N + col] = hh;
                }
            }
        }
    }
}

// =====================================================================
// Row LayerNorm over first 2048 cols + tail passthrough. __half output.
// =====================================================================
__global__ void __launch_bounds__(256)
ln_rows(const float* __restrict__ in, __half* __restrict__ out,
        const float* __restrict__ g, const float* __restrict__ b,
        const float* __restrict__ tail_src,
        int in_stride, int out_stride, int tail_stride, int tail_len)
{
    const int row = blockIdx.x;
    const int tid = threadIdx.x;
    const float* x = in + (size_t)row * in_stride;

    const float4 va = *(const float4*)&x[tid * 4];
    const float4 vb = *(const float4*)&x[(tid + 256) * 4];

    double s  = (double)va.x + va.y + va.z + va.w + (double)vb.x + vb.y + vb.z + vb.w;
    double ss = (double)va.x * va.x + (double)va.y * va.y + (double)va.z * va.z + (double)va.w * va.w
              + (double)vb.x * vb.x + (double)vb.y * vb.y + (double)vb.z * vb.z + (double)vb.w * vb.w;

#pragma unroll
    for (int off = 16; off; off >>= 1) {
        s  += __shfl_down_sync(0xffffffffu, s, off);
        ss += __shfl_down_sync(0xffffffffu, ss, off);
    }
    __shared__ double rs[8], rss[8];
    __shared__ float s_mean, s_rstd;
    const int warp = tid >> 5, lane = tid & 31;
    if (lane == 0) { rs[warp] = s; rss[warp] = ss; }
    __syncthreads();
    if (tid == 0) {
        double S = 0.0, SQ = 0.0;
        for (int w = 0; w < 8; w++) { S += rs[w]; SQ += rss[w]; }
        const double mean = S / 2048.0;
        const double var  = SQ / 2048.0 - mean * mean;
        s_mean = (float)mean;
        s_rstd = (float)(1.0 / sqrt(var + 1e-5));
    }
    __syncthreads();
    const float mean = s_mean, rstd = s_rstd;

    __half* o = out + (size_t)row * out_stride;
    {
        const int c0 = tid * 4;
        const float4 g4 = *(const float4*)&g[c0];
        const float4 b4 = *(const float4*)&b[c0];
        __half2 h0 = __floats2half2_rn((va.x - mean) * rstd * g4.x + b4.x,
                                       (va.y - mean) * rstd * g4.y + b4.y);
        __half2 h1 = __floats2half2_rn((va.z - mean) * rstd * g4.z + b4.z,
                                       (va.w - mean) * rstd * g4.w + b4.w);
        *(__half2*)&o[c0]     = h0;
        *(__half2*)&o[c0 + 2] = h1;
    }
    {
        const int c1 = (tid + 256) * 4;
        const float4 g4 = *(const float4*)&g[c1];
        const float4 b4 = *(const float4*)&b[c1];
        __half2 h0 = __floats2half2_rn((vb.x - mean) * rstd * g4.x + b4.x,
                                       (vb.y - mean) * rstd * g4.y + b4.y);
        __half2 h1 = __floats2half2_rn((vb.z - mean) * rstd * g4.z + b4.z,
                                       (vb.w - mean) * rstd * g4.w + b4.w);
        *(__half2*)&o[c1]     = h0;
        *(__half2*)&o[c1 + 2] = h1;
    }
    if (tail_len) {
        for (int c = tid; c < tail_len; c += 256)
            o[2048 + c] = __float2half_rn(tail_src[(size_t)row * tail_stride + 2048 + c]);
    }
}

// =====================================================================
// Attention: one CTA per batch; softmax over SLOT axis per pano column.
// =====================================================================
#define ATT 384
__global__ void __launch_bounds__(ATT)
attn_kernel(const float* __restrict__ q, const float* __restrict__ k,
            const float* __restrict__ v, const unsigned char* __restrict__ mask,
            __half* __restrict__ updates, float* __restrict__ attn_out)
{
    const int b = blockIdx.x;
    const int tid = threadIdx.x;

    __shared__ float qs[10][65];
    __shared__ float ks[36][65];
    __shared__ float dots[10][37];
    __shared__ float attns[10][37];

    const int i = tid / 36;
    const int j = tid % 36;
    float acc = 0.f;

    for (int d0 = 0; d0 < DD; d0 += 64) {
        for (int t = tid; t < 640; t += ATT) {
            const int r = t >> 6, c = t & 63;
            qs[r][c] = q[(size_t)(b * 10 + r) * DD + d0 + c];
        }
        for (int t = tid; t < 2304; t += ATT) {
            const int r = t >> 6, c = t & 63;
            ks[r][c] = k[(size_t)(b * 36 + r) * DD + d0 + c];
        }
        __syncthreads();
        if (tid < 360) {
#pragma unroll 16
            for (int dd = 0; dd < 64; dd++)
                acc += qs[i][dd] * ks[j][dd];
        }
        __syncthreads();
    }
    if (tid < 360) dots[i][j] = acc;
    __syncthreads();

    if (tid < 36) {
        const float scale = rsqrtf(2176.0f);
        const int jj = tid;
        bool m[10];
        float dv[10];
        float mx = -3.402823466e38f;
#pragma unroll
        for (int ii = 0; ii < 10; ii++) {
            m[ii] = (mask[b * 10 + ii] != 0);
            dv[ii] = dots[ii][jj] * scale;
            if (!m[ii]) mx = fmaxf(mx, dv[ii]);
        }
        float e[10], sum = 0.f;
#pragma unroll
        for (int ii = 0; ii < 10; ii++) {
            e[ii] = m[ii] ? 0.f : expf(dv[ii] - mx);
            sum += e[ii];
        }
        const float inv = 1.f / sum;
#pragma unroll
        for (int ii = 0; ii < 10; ii++) {
            const float a = e[ii] * inv;
            attns[ii][jj] = a;
            attn_out[(size_t)(b * 10 + ii) * 36 + jj] = a;
        }
    }
    __syncthreads();

    for (int d = tid; d < DD; d += ATT) {
        float u[10];
#pragma unroll
        for (int ii = 0; ii < 10; ii++) u[ii] = 0.f;
        for (int jj = 0; jj < 36; jj++) {
            const float vv = v[(size_t)(b * 36 + jj) * DD + d];
#pragma unroll
            for (int ii = 0; ii < 10; ii++) u[ii] += attns[ii][jj] * vv;
        }
#pragma unroll
        for (int ii = 0; ii < 10; ii++)
            updates[(size_t)(b * 10 + ii) * DD + d] = __float2half_rn(u[ii]);
    }
}

// ---------------- GRU elementwise ----------------
__global__ void __launch_bounds__(256)
gru_kernel(const float* __restrict__ gi, const float* __restrict__ gh,
           const float* __restrict__ h, float* __restrict__ hnew)
{
    const size_t idx = (size_t)blockIdx.x * 256 + threadIdx.x;
    const size_t row = idx >> 11;
    const size_t f   = idx & 2047;
    const size_t gb  = row * (size_t)F3 + f;
    const float ir = gi[gb], iz = gi[gb + 2048], in_ = gi[gb + 4096];
    const float hr = gh[gb], hz = gh[gb + 2048], hn  = gh[gb + 4096];
    const float r = 1.f / (1.f + expf(-(ir + hr)));
    const float z = 1.f / (1.f + expf(-(iz + hz)));
    const float n = tanhf(in_ + r * hn);
    hnew[idx] = (1.f - z) * n + z * h[idx];
}

// ---------------- misc copies ----------------
__global__ void __launch_bounds__(256)
init_h(const float* __restrict__ cand, float* __restrict__ h, __half* __restrict__ hr)
{
    const size_t idx = (size_t)blockIdx.x * 256 + threadIdx.x;
    const size_t row = idx >> 11;
    const size_t f   = idx & 2047;
    const float x = cand[row * (size_t)DD + f];
    h[idx]  = x;
    hr[idx] = __float2half_rn(x);
}

// copy angle tail (cols 2048..2175) into out
__global__ void __launch_bounds__(256)
angle_tail(const float* __restrict__ cand, float* __restrict__ out)
{
    const int idx = blockIdx.x * 256 + threadIdx.x;   // MROW*128
    const int row = idx >> 7;
    const int c   = idx & 127;
    const size_t o = (size_t)row * DD + 2048 + c;
    out[o] = cand[o];
}

// =====================================================================
// launch
// =====================================================================
extern "C" void kernel_launch(void* const* d_in, const int* in_sizes, int n_in,
                              void* d_out, int out_size)
{
    const float* cand  = (const float*)d_in[0];
    const float* pano  = (const float*)d_in[1];
    const void*  maskp = d_in[2];
    const float* Wq = (const float*)d_in[3];  const float* bq = (const float*)d_in[4];
    const float* Wk = (const float*)d_in[5];  const float* bk = (const float*)d_in[6];
    const float* Wv = (const float*)d_in[7];  const float* bv = (const float*)d_in[8];
    const float* W_ih = (const float*)d_in[9];  const float* b_ih = (const float*)d_in[10];
    const float* W_hh = (const float*)d_in[11]; const float* b_hh = (const float*)d_in[12];
    const float* W1 = (const float*)d_in[13]; const float* b1 = (const float*)d_in[14];
    const float* W2 = (const float*)d_in[15]; const float* b2 = (const float*)d_in[16];
    const float* ln_in_g = (const float*)d_in[17]; const float* ln_in_b = (const float*)d_in[18];
    const float* ln_sl_g = (const float*)d_in[19]; const float* ln_sl_b = (const float*)d_in[20];
    const float* ln_pr_g = (const float*)d_in[21]; const float* ln_pr_b = (const float*)d_in[22];

    float* out      = (float*)d_out;
    float* out_attn = out + (size_t)MROW * DD;

    __half *p_pano, *p_s, *p_upd, *p_t1, *p_hr, *p_pre, *p_w;
    float *p_k, *p_v, *p_q, *p_gi, *p_gh, *p_h, *p_hnew;
    unsigned char* p_mask;
    cudaGetSymbolAddress((void**)&p_pano, g_pano_ln);
    cudaGetSymbolAddress((void**)&p_k,    g_k);
    cudaGetSymbolAddress((void**)&p_v,    g_v);
    cudaGetSymbolAddress((void**)&p_s,    g_s);
    cudaGetSymbolAddress((void**)&p_q,    g_q);
    cudaGetSymbolAddress((void**)&p_upd,  g_upd);
    cudaGetSymbolAddress((void**)&p_t1,   g_t1);
    cudaGetSymbolAddress((void**)&p_gi,   g_gi);
    cudaGetSymbolAddress((void**)&p_gh,   g_gh);
    cudaGetSymbolAddress((void**)&p_h,    g_h);
    cudaGetSymbolAddress((void**)&p_hr,   g_hr);
    cudaGetSymbolAddress((void**)&p_hnew, g_hnew);
    cudaGetSymbolAddress((void**)&p_pre,  g_pre);
    cudaGetSymbolAddress((void**)&p_w,    g_wh);
    cudaGetSymbolAddress((void**)&p_mask, g_mask);

    cudaFuncSetAttribute(gemm_fp16, cudaFuncAttributeMaxDynamicSharedMemorySize, GEMM_DSMEM);

    // fp16 weight copies (single fused launch)
    __half* rWq = p_w;
    __half* rWk = rWq + SZ_QKV;
    __half* rWv = rWk + SZ_QKV;
    __half* rWih = rWv + SZ_QKV;
    __half* rWhh = rWih + SZ_IH;
    __half* rW1  = rWhh + SZ_HH;
    __half* rW2  = rW1 + SZ_W1;
    {
        const size_t n4 = SZ_TOT / 4;
        half_copy_all<<<(unsigned)((n4 + 255) / 256), 256>>>(Wq, Wk, Wv, W_ih, W_hh, W1, W2, p_w);
    }

    // mask dtype detection + canonicalization
    detect_mask<<<1, 256>>>((const unsigned char*)maskp);
    normalize_mask<<<(MROW + 255) / 256, 256>>>(maskp);

    // pano LN (fp16 out; consumed only as GEMM A for k/v)
    ln_rows<<<PROW, 256>>>(pano, p_pano, ln_in_g, ln_in_b, pano, DD, DD, DD, DD - FF);

    // k, v projections
    {
        dim3 grd(DD / 128, PROW / 128);
        gemm_fp16<<<grd, 128, GEMM_DSMEM>>>(p_pano, rWk, bk, nullptr, p_k, nullptr, PROW, DD, DD, DD, 0);
        gemm_fp16<<<grd, 128, GEMM_DSMEM>>>(p_pano, rWv, bv, nullptr, p_v, nullptr, PROW, DD, DD, DD, 0);
    }

    // h0 = cand[..., :F] (f32 + fp16 shadow)
    init_h<<<(MROW * FF) / 256, 256>>>(cand, p_h, p_hr);

    for (int it = 0; it < 3; it++) {
        ln_rows<<<MROW, 256>>>(p_h, p_s, ln_sl_g, ln_sl_b, cand, FF, DD, DD, DD - FF);
        {
            dim3 grd(DD / 128, MROW / 128);
            gemm_fp16<<<grd, 128, GEMM_DSMEM>>>(p_s, rWq, bq, nullptr, p_q, nullptr, MROW, DD, DD, DD, 0);
        }
        attn_kernel<<<BB, ATT>>>(p_q, p_k, p_v, p_mask, p_upd, out_attn);
        {
            dim3 grd(F3 / 128, MROW / 128);
            gemm_fp16<<<grd, 128, GEMM_DSMEM>>>(p_upd, rWih, b_ih, nullptr, p_gi, nullptr, MROW, F3, DD, F3, 0);
            gemm_fp16<<<grd, 128, GEMM_DSMEM>>>(p_hr,  rWhh, b_hh, nullptr, p_gh, nullptr, MROW, F3, FF, F3, 0);
        }
        gru_kernel<<<(MROW * FF) / 256, 256>>>(p_gi, p_gh, p_h, p_hnew);
        ln_rows<<<MROW, 256>>>(p_hnew, p_pre, ln_pr_g, ln_pr_b, nullptr, FF, FF, 0, 0);
        {
            dim3 grd(HH / 128, MROW / 128);
            gemm_fp16<<<grd, 128, GEMM_DSMEM>>>(p_pre, rW1, b1, nullptr, nullptr, p_t1, MROW, HH, FF, HH, 1);
        }
        {
            dim3 grd(FF / 128, MROW / 128);
            // last iteration: write h directly into out (stride DD)
            float* cf = (it == 2) ? out : p_h;
            int ldc  = (it == 2) ? DD : FF;
            gemm_fp16<<<grd, 128, GEMM_DSMEM>>>(p_t1, rW2, b2, p_hnew, cf, p_hr, MROW, FF, HH, ldc, 2);
        }
    }

    // angle tail of slots output
    angle_tail<<<(MROW * 128) / 256, 256>>>(cand, out);
}

// round 9
// speedup vs baseline: 3.1310x; 1.1839x over previous
#include <cuda_runtime.h>
#include <cuda_fp16.h>
#include <cstdint>
#include <cstddef>

// ---------------- problem constants ----------------
#define BB   1024
#define SS   10
#define NN   36
#define FF   2048
#define DD   2176
#define HH   2176
#define F3   6144
#define MROW (BB*SS)          // 10240
#define PROW (BB*NN)          // 36864

#define SZ_QKV (2176*2176)
#define SZ_IH  (6144*2176)
#define SZ_HH  (6144*2048)
#define SZ_W1  (2176*2048)
#define SZ_W2  (2048*2176)
#define SZ_TOT ((size_t)3*SZ_QKV + SZ_IH + SZ_HH + SZ_W1 + SZ_W2)

// ---------------- scratch (device globals; no allocation allowed) --------
__device__ __half g_pano_ln[(size_t)PROW * DD];
__device__ float  g_k      [(size_t)PROW * DD];
__device__ __half g_v      [(size_t)PROW * DD];
__device__ __half g_s      [(size_t)MROW * DD];
__device__ float  g_q      [(size_t)MROW * DD];
__device__ __half g_upd    [(size_t)MROW * DD];
__device__ __half g_t1     [(size_t)MROW * HH];
__device__ float  g_gi     [(size_t)MROW * F3];
__device__ float  g_gh     [(size_t)MROW * F3];
__device__ float  g_h      [(size_t)MROW * FF];
__device__ __half g_hr     [(size_t)MROW * FF];
__device__ float  g_hnew   [(size_t)MROW * FF];
__device__ __half g_pre    [(size_t)MROW * FF];
__device__ __half g_wh     [SZ_TOT];
__device__ int            g_mask_mode;
__device__ unsigned char  g_mask[MROW];

// ---------------- helpers ----------------
__device__ __forceinline__ void cp16(void* dst, const void* src) {
    uint32_t d = (uint32_t)__cvta_generic_to_shared(dst);
    asm volatile("cp.async.cg.shared.global [%0], [%1], 16;" :: "r"(d), "l"(src));
}

__device__ __forceinline__ uint32_t smem_u32(const void* p) {
    uint32_t a;
    asm("{ .reg .u64 t; cvta.to.shared.u64 t, %1; cvt.u32.u64 %0, t; }" : "=r"(a) : "l"(p));
    return a;
}

__device__ __forceinline__ void ldsm4(uint32_t& d0, uint32_t& d1, uint32_t& d2,
                                      uint32_t& d3, uint32_t addr) {
    asm volatile("ldmatrix.sync.aligned.m8n8.x4.shared.b16 {%0,%1,%2,%3}, [%4];"
                 : "=r"(d0), "=r"(d1), "=r"(d2), "=r"(d3) : "r"(addr));
}

// =====================================================================
// Mask dtype detection + normalization (bool widened to unknown dtype).
// =====================================================================
__global__ void detect_mask(const unsigned char* __restrict__ m)
{
    __shared__ int has1, has23;
    if (threadIdx.x == 0) { has1 = 0; has23 = 0; }
    __syncthreads();
    for (int i = threadIdx.x; i < MROW; i += 256) {
        if (m[i]) {
            const int p = i & 3;
            if (p == 1) atomicOr(&has1, 1);
            if (p >= 2) atomicOr(&has23, 1);
        }
    }
    __syncthreads();
    if (threadIdx.x == 0)
        g_mask_mode = has1 ? 1 : (has23 ? 2 : 0);
}

__global__ void normalize_mask(const void* __restrict__ m)
{
    const int i = blockIdx.x * 256 + threadIdx.x;
    if (i >= MROW) return;
    const int mode = g_mask_mode;
    unsigned char r;
    if (mode == 1)      r = (((const unsigned char*)m)[i] != 0);
    else if (mode == 2) r = (((const float*)m)[i] != 0.0f);
    else                r = (((const int*)m)[i] != 0);
    g_mask[i] = r;
}

// ---------------- fused fp16 weight copy (single launch) ----------------
__global__ void __launch_bounds__(256)
half_copy_all(const float* s0, const float* s1, const float* s2,
              const float* s3, const float* s4, const float* s5,
              const float* s6, __half* __restrict__ d)
{
    const size_t seg_end[7] = {
        (size_t)SZ_QKV, (size_t)2*SZ_QKV, (size_t)3*SZ_QKV,
        (size_t)3*SZ_QKV + SZ_IH,
        (size_t)3*SZ_QKV + SZ_IH + SZ_HH,
        (size_t)3*SZ_QKV + SZ_IH + SZ_HH + SZ_W1,
        SZ_TOT };
    const float* srcs[7] = { s0, s1, s2, s3, s4, s5, s6 };

    const size_t i4 = (size_t)blockIdx.x * 256 + threadIdx.x;
    const size_t e0 = i4 * 4;
    if (e0 >= SZ_TOT) return;

    int seg = 0;
    size_t base = 0;
#pragma unroll
    for (int k = 0; k < 7; k++) {
        if (e0 >= seg_end[k]) { seg = k + 1; base = seg_end[k]; }
    }
    const float4 v = *(const float4*)(srcs[seg] + (e0 - base));
    __half2 h0 = __floats2half2_rn(v.x, v.y);
    __half2 h1 = __floats2half2_rn(v.z, v.w);
    uint2 o; o.x = *(uint32_t*)&h0; o.y = *(uint32_t*)&h1;
    *(uint2*)(d + e0) = o;
}

// =====================================================================
// FP16 GEMM: CTA 128x128, 128 thr (4 warps 2x2, warp 64x64).
// 3-stage cp.async ring, stage = k64. Fragment double-buffer. fp32 acc.
// mode 0: Cf(f32,ldC) = acc+bias
// mode 1: Ch(f16)     = relu(acc+bias)
// mode 2: Cf(f32,ldC) = acc+bias+addm ; Ch(f16) = same value
// mode 3: Ch(f16)     = acc+bias
// =====================================================================
#define STG_BYTES 32768
#define GEMM_DSMEM (3*STG_BYTES + 1024)

__device__ __forceinline__ void load_stage(const __half* __restrict__ A,
                                           const __half* __restrict__ W,
                                           int K, int bm0, int bn0, int kt,
                                           char* stg, int tid)
{
    const __half* Asrc = A + (size_t)bm0 * K + kt * 64;
    const __half* Wsrc = W + (size_t)bn0 * K + kt * 64;
#pragma unroll
    for (int i = 0; i < 8; i++) {
        const int idx = i * 128 + tid;
        const int row = idx >> 3;
        const int g   = idx & 7;
        const int perm = g ^ (row & 7);
        cp16(stg + row * 128 + perm * 16, Asrc + (size_t)row * K + g * 8);
    }
#pragma unroll
    for (int i = 0; i < 8; i++) {
        const int idx = i * 128 + tid;
        const int row = idx >> 3;
        const int g   = idx & 7;
        const int perm = g ^ (row & 7);
        cp16(stg + 16384 + row * 128 + perm * 16, Wsrc + (size_t)row * K + g * 8);
    }
    asm volatile("cp.async.commit_group;" ::: "memory");
}

__device__ __forceinline__ void load_frags(uint32_t stg, const uint32_t* oA,
                                           const uint32_t* oB,
                                           uint32_t a[4][4], uint32_t b[8][2])
{
#pragma unroll
    for (int mi = 0; mi < 4; mi++)
        ldsm4(a[mi][0], a[mi][1], a[mi][2], a[mi][3], stg + oA[mi]);
#pragma unroll
    for (int p = 0; p < 4; p++) {
        uint32_t d0, d1, d2, d3;
        ldsm4(d0, d1, d2, d3, stg + oB[p]);
        b[2 * p][0] = d0;     b[2 * p][1] = d2;
        b[2 * p + 1][0] = d1; b[2 * p + 1][1] = d3;
    }
}

__device__ __forceinline__ void do_mmas(const uint32_t a[4][4], const uint32_t b[8][2],
                                        float acc[4][8][4])
{
#pragma unroll
    for (int nj = 0; nj < 8; nj++) {
#pragma unroll
        for (int mi = 0; mi < 4; mi++) {
            asm volatile(
                "mma.sync.aligned.m16n8k16.row.col.f32.f16.f16.f32 "
                "{%0,%1,%2,%3},{%4,%5,%6,%7},{%8,%9},{%0,%1,%2,%3};\n"
                : "+f"(acc[mi][nj][0]), "+f"(acc[mi][nj][1]),
                  "+f"(acc[mi][nj][2]), "+f"(acc[mi][nj][3])
                : "r"(a[mi][0]), "r"(a[mi][1]), "r"(a[mi][2]), "r"(a[mi][3]),
                  "r"(b[nj][0]), "r"(b[nj][1]));
        }
    }
}

__global__ void __launch_bounds__(128, 2)
gemm_fp16(const __half* __restrict__ A, const __half* __restrict__ W,
          const float* __restrict__ bias, const float* __restrict__ addm,
          float* __restrict__ Cf, __half* __restrict__ Ch,
          int M, int N, int K, int ldC, int mode)
{
    extern __shared__ char smraw[];
    char* base = (char*)(((uintptr_t)smraw + 1023) & ~(uintptr_t)1023);
    const uint32_t sb = smem_u32(base);

    const int tid  = threadIdx.x;
    const int lane = tid & 31;
    const int warp = tid >> 5;
    const int wm   = warp >> 1;
    const int wn   = warp & 1;
    const int gid  = lane >> 2;
    const int tg   = lane & 3;
    const int mtx  = lane >> 3;
    const int rowin = lane & 7;

    const int bm0 = blockIdx.y * 128;
    const int bn0 = blockIdx.x * 128;

    uint32_t offA[4][4], offB[4][4];
#pragma unroll
    for (int ks = 0; ks < 4; ks++) {
#pragma unroll
        for (int mi = 0; mi < 4; mi++) {
            const int r = wm * 64 + mi * 16 + (mtx & 1) * 8 + rowin;
            const int g = ks * 2 + (mtx >> 1);
            offA[ks][mi] = (uint32_t)(r * 128 + ((g ^ (r & 7)) << 4));
        }
#pragma unroll
        for (int p = 0; p < 4; p++) {
            const int r = wn * 64 + p * 16 + (mtx & 1) * 8 + rowin;
            const int g = ks * 2 + (mtx >> 1);
            offB[ks][p] = (uint32_t)(16384 + r * 128 + ((g ^ (r & 7)) << 4));
        }
    }

    float acc[4][8][4];
#pragma unroll
    for (int mi = 0; mi < 4; mi++)
#pragma unroll
        for (int nj = 0; nj < 8; nj++)
#pragma unroll
            for (int c = 0; c < 4; c++) acc[mi][nj][c] = 0.f;

    const int nkt = K >> 6;

    load_stage(A, W, K, bm0, bn0, 0, base,             tid);
    load_stage(A, W, K, bm0, bn0, 1, base + STG_BYTES, tid);
    asm volatile("cp.async.wait_group 1;" ::: "memory");
    __syncthreads();

    uint32_t fa[2][4][4], fb[2][8][2];
    load_frags(sb, offA[0], offB[0], fa[0], fb[0]);

    int stg_i = 0;
    for (int kt = 0; kt < nkt; kt++) {
        const uint32_t stg = sb + (uint32_t)stg_i * STG_BYTES;
        const int stg_n = (stg_i == 2) ? 0 : stg_i + 1;

        if (kt + 2 < nkt) {
            const int stg_p = (stg_n == 2) ? 0 : stg_n + 1;
            load_stage(A, W, K, bm0, bn0, kt + 2, base + stg_p * STG_BYTES, tid);
        } else {
            asm volatile("cp.async.commit_group;" ::: "memory");
        }
        load_frags(stg, offA[1], offB[1], fa[1], fb[1]);
        do_mmas(fa[0], fb[0], acc);

        load_frags(stg, offA[2], offB[2], fa[0], fb[0]);
        do_mmas(fa[1], fb[1], acc);

        load_frags(stg, offA[3], offB[3], fa[1], fb[1]);
        do_mmas(fa[0], fb[0], acc);

        asm volatile("cp.async.wait_group 1;" ::: "memory");
        __syncthreads();
        if (kt + 1 < nkt)
            load_frags(sb + (uint32_t)stg_n * STG_BYTES, offA[0], offB[0], fa[0], fb[0]);
        do_mmas(fa[1], fb[1], acc);

        stg_i = stg_n;
    }

    // epilogue
#pragma unroll
    for (int mi = 0; mi < 4; mi++) {
#pragma unroll
        for (int nj = 0; nj < 8; nj++) {
            const int col = bn0 + wn * 64 + nj * 8 + tg * 2;
            const float2 bv = *(const float2*)&bias[col];
#pragma unroll
            for (int ch = 0; ch < 2; ch++) {
                const int row = bm0 + wm * 64 + mi * 16 + gid + ch * 8;
                float x0 = acc[mi][nj][ch * 2 + 0] + bv.x;
                float x1 = acc[mi][nj][ch * 2 + 1] + bv.y;
                if (mode == 0) {
                    float2 o; o.x = x0; o.y = x1;
                    *(float2*)&Cf[(size_t)row * ldC + col] = o;
                } else if (mode == 1) {
                    __half2 hh = __floats2half2_rn(fmaxf(x0, 0.f), fmaxf(x1, 0.f));
                    *(__half2*)&Ch[(size_t)row * N + col] = hh;
                } else if (mode == 2) {
                    const float2 av = *(const float2*)&addm[(size_t)row * N + col];
                    x0 += av.x; x1 += av.y;
                    float2 o; o.x = x0; o.y = x1;
                    *(float2*)&Cf[(size_t)row * ldC + col] = o;
                    __half2 hh = __floats2half2_rn(x0, x1);
                    *(__half2*)&Ch[(size_t)row * N + col] = hh;
                } else {
                    __half2 hh = __floats2half2_rn(x0, x1);
                    *(__half2*)&Ch[(size_t)row * N + col] = hh;
                }
            }
        }
    }
}

// =====================================================================
// Row LayerNorm over first 2048 cols + tail passthrough. fp32 math
// (matches reference precision), __half output.
// =====================================================================
__global__ void __launch_bounds__(256)
ln_rows(const float* __restrict__ in, __half* __restrict__ out,
        const float* __restrict__ g, const float* __restrict__ b,
        const float* __restrict__ tail_src,
        int in_stride, int out_stride, int tail_stride, int tail_len)
{
    const int row = blockIdx.x;
    const int tid = threadIdx.x;
    const float* x = in + (size_t)row * in_stride;

    const float4 va = *(const float4*)&x[tid * 4];
    const float4 vb = *(const float4*)&x[(tid + 256) * 4];

    float s  = (va.x + va.y) + (va.z + va.w) + (vb.x + vb.y) + (vb.z + vb.w);
    float ss = (va.x * va.x + va.y * va.y) + (va.z * va.z + va.w * va.w)
             + (vb.x * vb.x + vb.y * vb.y) + (vb.z * vb.z + vb.w * vb.w);

#pragma unroll
    for (int off = 16; off; off >>= 1) {
        s  += __shfl_down_sync(0xffffffffu, s, off);
        ss += __shfl_down_sync(0xffffffffu, ss, off);
    }
    __shared__ float rs[8], rss[8];
    __shared__ float s_mean, s_rstd;
    const int warp = tid >> 5, lane = tid & 31;
    if (lane == 0) { rs[warp] = s; rss[warp] = ss; }
    __syncthreads();
    if (warp == 0) {
        float S  = (lane < 8) ? rs[lane]  : 0.f;
        float SQ = (lane < 8) ? rss[lane] : 0.f;
#pragma unroll
        for (int off = 4; off; off >>= 1) {
            S  += __shfl_down_sync(0xffffffffu, S, off);
            SQ += __shfl_down_sync(0xffffffffu, SQ, off);
        }
        if (lane == 0) {
            const float mean = S * (1.f / 2048.f);
            const float var  = SQ * (1.f / 2048.f) - mean * mean;
            s_mean = mean;
            s_rstd = rsqrtf(var + 1e-5f);
        }
    }
    __syncthreads();
    const float mean = s_mean, rstd = s_rstd;

    __half* o = out + (size_t)row * out_stride;
    {
        const int c0 = tid * 4;
        const float4 g4 = *(const float4*)&g[c0];
        const float4 b4 = *(const float4*)&b[c0];
        __half2 h0 = __floats2half2_rn((va.x - mean) * rstd * g4.x + b4.x,
                                       (va.y - mean) * rstd * g4.y + b4.y);
        __half2 h1 = __floats2half2_rn((va.z - mean) * rstd * g4.z + b4.z,
                                       (va.w - mean) * rstd * g4.w + b4.w);
        *(__half2*)&o[c0]     = h0;
        *(__half2*)&o[c0 + 2] = h1;
    }
    {
        const int c1 = (tid + 256) * 4;
        const float4 g4 = *(const float4*)&g[c1];
        const float4 b4 = *(const float4*)&b[c1];
        __half2 h0 = __floats2half2_rn((vb.x - mean) * rstd * g4.x + b4.x,
                                       (vb.y - mean) * rstd * g4.y + b4.y);
        __half2 h1 = __floats2half2_rn((vb.z - mean) * rstd * g4.z + b4.z,
                                       (vb.w - mean) * rstd * g4.w + b4.w);
        *(__half2*)&o[c1]     = h0;
        *(__half2*)&o[c1 + 2] = h1;
    }
    if (tail_len) {
        for (int c = tid; c < tail_len; c += 256)
            o[2048 + c] = __float2half_rn(tail_src[(size_t)row * tail_stride + 2048 + c]);
    }
}

// =====================================================================
// Attention: one CTA per batch; softmax over SLOT axis per pano column.
// q,k fp32; v fp16; updates fp16.
// =====================================================================
#define ATT 384
__global__ void __launch_bounds__(ATT)
attn_kernel(const float* __restrict__ q, const float* __restrict__ k,
            const __half* __restrict__ v, const unsigned char* __restrict__ mask,
            __half* __restrict__ updates, float* __restrict__ attn_out)
{
    const int b = blockIdx.x;
    const int tid = threadIdx.x;

    __shared__ float qs[10][65];
    __shared__ float ks[36][65];
    __shared__ float dots[10][37];
    __shared__ float attns[10][37];

    const int i = tid / 36;
    const int j = tid % 36;
    float acc = 0.f;

    for (int d0 = 0; d0 < DD; d0 += 64) {
        for (int t = tid; t < 640; t += ATT) {
            const int r = t >> 6, c = t & 63;
            qs[r][c] = q[(size_t)(b * 10 + r) * DD + d0 + c];
        }
        for (int t = tid; t < 2304; t += ATT) {
            const int r = t >> 6, c = t & 63;
            ks[r][c] = k[(size_t)(b * 36 + r) * DD + d0 + c];
        }
        __syncthreads();
        if (tid < 360) {
#pragma unroll 16
            for (int dd = 0; dd < 64; dd++)
                acc += qs[i][dd] * ks[j][dd];
        }
        __syncthreads();
    }
    if (tid < 360) dots[i][j] = acc;
    __syncthreads();

    if (tid < 36) {
        const float scale = rsqrtf(2176.0f);
        const int jj = tid;
        bool m[10];
        float dv[10];
        float mx = -3.402823466e38f;
#pragma unroll
        for (int ii = 0; ii < 10; ii++) {
            m[ii] = (mask[b * 10 + ii] != 0);
            dv[ii] = dots[ii][jj] * scale;
            if (!m[ii]) mx = fmaxf(mx, dv[ii]);
        }
        float e[10], sum = 0.f;
#pragma unroll
        for (int ii = 0; ii < 10; ii++) {
            e[ii] = m[ii] ? 0.f : expf(dv[ii] - mx);
            sum += e[ii];
        }
        const float inv = 1.f / sum;
#pragma unroll
        for (int ii = 0; ii < 10; ii++) {
            const float a = e[ii] * inv;
            attns[ii][jj] = a;
            attn_out[(size_t)(b * 10 + ii) * 36 + jj] = a;
        }
    }
    __syncthreads();

    for (int d = tid; d < DD; d += ATT) {
        float u[10];
#pragma unroll
        for (int ii = 0; ii < 10; ii++) u[ii] = 0.f;
        for (int jj = 0; jj < 36; jj++) {
            const float vv = __half2float(v[(size_t)(b * 36 + jj) * DD + d]);
#pragma unroll
            for (int ii = 0; ii < 10; ii++) u[ii] += attns[ii][jj] * vv;
        }
#pragma unroll
        for (int ii = 0; ii < 10; ii++)
            updates[(size_t)(b * 10 + ii) * DD + d] = __float2half_rn(u[ii]);
    }
}

// ---------------- GRU elementwise (float4) ----------------
__global__ void __launch_bounds__(256)
gru_kernel(const float* __restrict__ gi, const float* __restrict__ gh,
           const float* __restrict__ h, float* __restrict__ hnew)
{
    const size_t i4  = (size_t)blockIdx.x * 256 + threadIdx.x;  // float4 index
    const size_t row = i4 >> 9;               // 512 float4 per row (2048 floats)
    const size_t f   = (i4 & 511) << 2;
    const size_t gb  = (row * (size_t)F3 + f) >> 2;
    const size_t hb  = i4;

    const float4 ir4 = ((const float4*)gi)[gb];
    const float4 iz4 = ((const float4*)gi)[gb + 512];
    const float4 in4 = ((const float4*)gi)[gb + 1024];
    const float4 hr4 = ((const float4*)gh)[gb];
    const float4 hz4 = ((const float4*)gh)[gb + 512];
    const float4 hn4 = ((const float4*)gh)[gb + 1024];
    const float4 h4  = ((const float4*)h)[hb];

    float4 o;
    {
        const float r = 1.f / (1.f + expf(-(ir4.x + hr4.x)));
        const float z = 1.f / (1.f + expf(-(iz4.x + hz4.x)));
        const float n = tanhf(in4.x + r * hn4.x);
        o.x = (1.f - z) * n + z * h4.x;
    }
    {
        const float r = 1.f / (1.f + expf(-(ir4.y + hr4.y)));
        const float z = 1.f / (1.f + expf(-(iz4.y + hz4.y)));
        const float n = tanhf(in4.y + r * hn4.y);
        o.y = (1.f - z) * n + z * h4.y;
    }
    {
        const float r = 1.f / (1.f + expf(-(ir4.z + hr4.z)));
        const float z = 1.f / (1.f + expf(-(iz4.z + hz4.z)));
        const float n = tanhf(in4.z + r * hn4.z);
        o.z = (1.f - z) * n + z * h4.z;
    }
    {
        const float r = 1.f / (1.f + expf(-(ir4.w + hr4.w)));
        const float z = 1.f / (1.f + expf(-(iz4.w + hz4.w)));
        const float n = tanhf(in4.w + r * hn4.w);
        o.w = (1.f - z) * n + z * h4.w;
    }
    ((float4*)hnew)[hb] = o;
}

// ---------------- misc copies ----------------
__global__ void __launch_bounds__(256)
init_h(const float* __restrict__ cand, float* __restrict__ h, __half* __restrict__ hr)
{
    const size_t idx = (size_t)blockIdx.x * 256 + threadIdx.x;
    const size_t row = idx >> 11;
    const size_t f   = idx & 2047;
    const float x = cand[row * (size_t)DD + f];
    h[idx]  = x;
    hr[idx] = __float2half_rn(x);
}

__global__ void __launch_bounds__(256)
angle_tail(const float* __restrict__ cand, float* __restrict__ out)
{
    const int idx = blockIdx.x * 256 + threadIdx.x;   // MROW*128
    const int row = idx >> 7;
    const int c   = idx & 127;
    const size_t o = (size_t)row * DD + 2048 + c;
    out[o] = cand[o];
}

// =====================================================================
// launch
// =====================================================================
extern "C" void kernel_launch(void* const* d_in, const int* in_sizes, int n_in,
                              void* d_out, int out_size)
{
    const float* cand  = (const float*)d_in[0];
    const float* pano  = (const float*)d_in[1];
    const void*  maskp = d_in[2];
    const float* Wq = (const float*)d_in[3];  const float* bq = (const float*)d_in[4];
    const float* Wk = (const float*)d_in[5];  const float* bk = (const float*)d_in[6];
    const float* Wv = (const float*)d_in[7];  const float* bv = (const float*)d_in[8];
    const float* W_ih = (const float*)d_in[9];  const float* b_ih = (const float*)d_in[10];
    const float* W_hh = (const float*)d_in[11]; const float* b_hh = (const float*)d_in[12];
    const float* W1 = (const float*)d_in[13]; const float* b1 = (const float*)d_in[14];
    const float* W2 = (const float*)d_in[15]; const float* b2 = (const float*)d_in[16];
    const float* ln_in_g = (const float*)d_in[17]; const float* ln_in_b = (const float*)d_in[18];
    const float* ln_sl_g = (const float*)d_in[19]; const float* ln_sl_b = (const float*)d_in[20];
    const float* ln_pr_g = (const float*)d_in[21]; const float* ln_pr_b = (const float*)d_in[22];

    float* out      = (float*)d_out;
    float* out_attn = out + (size_t)MROW * DD;

    __half *p_pano, *p_v, *p_s, *p_upd, *p_t1, *p_hr, *p_pre, *p_w;
    float *p_k, *p_q, *p_gi, *p_gh, *p_h, *p_hnew;
    unsigned char* p_mask;
    cudaGetSymbolAddress((void**)&p_pano, g_pano_ln);
    cudaGetSymbolAddress((void**)&p_k,    g_k);
    cudaGetSymbolAddress((void**)&p_v,    g_v);
    cudaGetSymbolAddress((void**)&p_s,    g_s);
    cudaGetSymbolAddress((void**)&p_q,    g_q);
    cudaGetSymbolAddress((void**)&p_upd,  g_upd);
    cudaGetSymbolAddress((void**)&p_t1,   g_t1);
    cudaGetSymbolAddress((void**)&p_gi,   g_gi);
    cudaGetSymbolAddress((void**)&p_gh,   g_gh);
    cudaGetSymbolAddress((void**)&p_h,    g_h);
    cudaGetSymbolAddress((void**)&p_hr,   g_hr);
    cudaGetSymbolAddress((void**)&p_hnew, g_hnew);
    cudaGetSymbolAddress((void**)&p_pre,  g_pre);
    cudaGetSymbolAddress((void**)&p_w,    g_wh);
    cudaGetSymbolAddress((void**)&p_mask, g_mask);

    cudaFuncSetAttribute(gemm_fp16, cudaFuncAttributeMaxDynamicSharedMemorySize, GEMM_DSMEM);

    // fp16 weight copies (single fused launch)
    __half* rWq = p_w;
    __half* rWk = rWq + SZ_QKV;
    __half* rWv = rWk + SZ_QKV;
    __half* rWih = rWv + SZ_QKV;
    __half* rWhh = rWih + SZ_IH;
    __half* rW1  = rWhh + SZ_HH;
    __half* rW2  = rW1 + SZ_W1;
    {
        const size_t n4 = SZ_TOT / 4;
        half_copy_all<<<(unsigned)((n4 + 255) / 256), 256>>>(Wq, Wk, Wv, W_ih, W_hh, W1, W2, p_w);
    }

    // mask dtype detection + canonicalization
    detect_mask<<<1, 256>>>((const unsigned char*)maskp);
    normalize_mask<<<(MROW + 255) / 256, 256>>>(maskp);

    // pano LN (fp16 out; consumed only as GEMM A for k/v)
    ln_rows<<<PROW, 256>>>(pano, p_pano, ln_in_g, ln_in_b, pano, DD, DD, DD, DD - FF);

    // k (f32), v (f16) projections
    {
        dim3 grd(DD / 128, PROW / 128);
        gemm_fp16<<<grd, 128, GEMM_DSMEM>>>(p_pano, rWk, bk, nullptr, p_k, nullptr, PROW, DD, DD, DD, 0);
        gemm_fp16<<<grd, 128, GEMM_DSMEM>>>(p_pano, rWv, bv, nullptr, nullptr, p_v, PROW, DD, DD, DD, 3);
    }

    // h0 = cand[..., :F] (f32 + fp16 shadow)
    init_h<<<(MROW * FF) / 256, 256>>>(cand, p_h, p_hr);

    for (int it = 0; it < 3; it++) {
        ln_rows<<<MROW, 256>>>(p_h, p_s, ln_sl_g, ln_sl_b, cand, FF, DD, DD, DD - FF);
        {
            dim3 grd(DD / 128, MROW / 128);
            gemm_fp16<<<grd, 128, GEMM_DSMEM>>>(p_s, rWq, bq, nullptr, p_q, nullptr, MROW, DD, DD, DD, 0);
        }
        attn_kernel<<<BB, ATT>>>(p_q, p_k, p_v, p_mask, p_upd, out_attn);
        {
            dim3 grd(F3 / 128, MROW / 128);
            gemm_fp16<<<grd, 128, GEMM_DSMEM>>>(p_upd, rWih, b_ih, nullptr, p_gi, nullptr, MROW, F3, DD, F3, 0);
            gemm_fp16<<<grd, 128, GEMM_DSMEM>>>(p_hr,  rWhh, b_hh, nullptr, p_gh, nullptr, MROW, F3, FF, F3, 0);
        }
        gru_kernel<<<(MROW * FF / 4) / 256, 256>>>(p_gi, p_gh, p_h, p_hnew);
        ln_rows<<<MROW, 256>>>(p_hnew, p_pre, ln_pr_g, ln_pr_b, nullptr, FF, FF, 0, 0);
        {
            dim3 grd(HH / 128, MROW / 128);
            gemm_fp16<<<grd, 128, GEMM_DSMEM>>>(p_pre, rW1, b1, nullptr, nullptr, p_t1, MROW, HH, FF, HH, 1);
        }
        {
            dim3 grd(FF / 128, MROW / 128);
            float* cf = (it == 2) ? out : p_h;
            int ldc  = (it == 2) ? DD : FF;
            gemm_fp16<<<grd, 128, GEMM_DSMEM>>>(p_t1, rW2, b2, p_hnew, cf, p_hr, MROW, FF, HH, ldc, 2);
        }
    }

    // angle tail of slots output
    angle_tail<<<(MROW * 128) / 256, 256>>>(cand, out);
}